// round 1
// baseline (speedup 1.0000x reference)
#include <cuda_runtime.h>
#include <mma.h>

using namespace nvcuda;

#define NT 20000
#define NC 80000
#define DIM 256
#define E_T2C 320000
#define E_C2T 320000
#define E_C2C 640000
#define E_T2T 160000

// ---------------- scratch (device globals; no allocations allowed) ----------
__device__ float g_Wh_t2c[(size_t)NT * DIM];
__device__ float g_Wh_c2t[(size_t)NC * DIM];
__device__ float g_Wh_c2c[(size_t)NC * DIM];
__device__ float g_Wh_t2t[(size_t)NT * DIM];
__device__ float g_h_tab[(size_t)NT * DIM];
__device__ float g_h_col[(size_t)NC * DIM];

__device__ int g_cnt_t2c[NC];     __device__ int g_off_t2c[NC + 1]; __device__ int g_pos_t2c[NC]; __device__ int g_e_t2c[E_T2C];
__device__ int g_cnt_c2t[NT];     __device__ int g_off_c2t[NT + 1]; __device__ int g_pos_c2t[NT]; __device__ int g_e_c2t[E_C2T];
__device__ int g_cnt_c2c[NC];     __device__ int g_off_c2c[NC + 1]; __device__ int g_pos_c2c[NC]; __device__ int g_e_c2c[E_C2C];
__device__ int g_cnt_t2t[NT];     __device__ int g_off_t2t[NT + 1]; __device__ int g_pos_t2t[NT]; __device__ int g_e_t2t[E_T2T];

// ---------------- small helpers ---------------------------------------------
__global__ void hist_kernel(const int* __restrict__ dst, int* __restrict__ cnt, int E) {
    int i = blockIdx.x * blockDim.x + threadIdx.x;
    if (i < E) atomicAdd(&cnt[dst[i]], 1);
}

// single-block exclusive scan (n up to 80000): cnt -> off (and pos copy)
__global__ void exscan_kernel(const int* __restrict__ cnt, int* __restrict__ off,
                              int* __restrict__ pos, int n) {
    __shared__ int sh[1024];
    __shared__ int carry;
    int tid = threadIdx.x;
    if (tid == 0) carry = 0;
    __syncthreads();
    for (int base = 0; base < n; base += 1024) {
        int i = base + tid;
        int v = (i < n) ? cnt[i] : 0;
        int x = v;
        #pragma unroll
        for (int ofs = 1; ofs < 1024; ofs <<= 1) {
            sh[tid] = x;
            __syncthreads();
            if (tid >= ofs) x += sh[tid - ofs];
            __syncthreads();
        }
        int excl = carry + x - v;
        if (i < n) { off[i] = excl; pos[i] = excl; }
        __syncthreads();
        if (tid == 1023) carry += x;   // x at tid 1023 == chunk total (inclusive)
        __syncthreads();
    }
    if (tid == 0) off[n] = carry;
}

__global__ void build_kernel(const int* __restrict__ src, const int* __restrict__ dst,
                             int* __restrict__ pos, int* __restrict__ eidx, int E) {
    int i = blockIdx.x * blockDim.x + threadIdx.x;
    if (i < E) {
        int slot = atomicAdd(&pos[dst[i]], 1);
        eidx[slot] = src[i];
    }
}

// ---------------- GEMM: C = lrelu(A @ W^T + b) (+ residual) -----------------
// A: [M,256] row-major, W: [256,256] row-major (so B = W^T is col-major with ld 256)
// grid: (M/32, 2), block 256. BLOCK_M=32, BLOCK_N=128, KC=32, tf32 wmma m16n16k8.
template <bool RES>
__global__ void gemm_lrelu_kernel(const float* __restrict__ A, const float* __restrict__ W,
                                  const float* __restrict__ bias, const float* __restrict__ resid,
                                  float* __restrict__ C) {
    const int bm = blockIdx.x, bn = blockIdx.y;
    __shared__ float As[32][36];
    __shared__ float Bs[128][36];
    __shared__ float Cs[32][132];

    const int t = threadIdx.x;
    const int wid = t >> 5;
    const int wm = wid >> 2;      // 0..1
    const int wn = wid & 3;       // 0..3

    wmma::fragment<wmma::accumulator, 16, 16, 8, float> c0, c1;
    wmma::fill_fragment(c0, 0.0f);
    wmma::fill_fragment(c1, 0.0f);

    for (int kb = 0; kb < 8; kb++) {
        // load A tile: 32x32 = 256 float4, one per thread
        {
            int row = t >> 3, c4 = t & 7;
            *(float4*)&As[row][c4 * 4] =
                *(const float4*)&A[(size_t)(bm * 32 + row) * DIM + kb * 32 + c4 * 4];
        }
        // load B tile (W rows are the N dim): 128x32 = 1024 float4, 4 per thread
        #pragma unroll
        for (int i = 0; i < 4; i++) {
            int idx = t + i * 256;
            int n = idx >> 3, cc = idx & 7;
            *(float4*)&Bs[n][cc * 4] =
                *(const float4*)&W[(size_t)(bn * 128 + n) * DIM + kb * 32 + cc * 4];
        }
        __syncthreads();

        #pragma unroll
        for (int kk = 0; kk < 4; kk++) {
            wmma::fragment<wmma::matrix_a, 16, 16, 8, wmma::precision::tf32, wmma::row_major> a;
            wmma::fragment<wmma::matrix_b, 16, 16, 8, wmma::precision::tf32, wmma::col_major> b0, b1;
            wmma::load_matrix_sync(a, &As[wm * 16][kk * 8], 36);
            wmma::load_matrix_sync(b0, &Bs[wn * 32][kk * 8], 36);
            wmma::load_matrix_sync(b1, &Bs[wn * 32 + 16][kk * 8], 36);
            #pragma unroll
            for (int i = 0; i < a.num_elements; i++) a.x[i] = wmma::__float_to_tf32(a.x[i]);
            #pragma unroll
            for (int i = 0; i < b0.num_elements; i++) b0.x[i] = wmma::__float_to_tf32(b0.x[i]);
            #pragma unroll
            for (int i = 0; i < b1.num_elements; i++) b1.x[i] = wmma::__float_to_tf32(b1.x[i]);
            wmma::mma_sync(c0, a, b0, c0);
            wmma::mma_sync(c1, a, b1, c1);
        }
        __syncthreads();
    }

    wmma::store_matrix_sync(&Cs[wm * 16][wn * 32], c0, 132, wmma::mem_row_major);
    wmma::store_matrix_sync(&Cs[wm * 16][wn * 32 + 16], c1, 132, wmma::mem_row_major);
    __syncthreads();

    // epilogue: bias + leaky_relu (+ residual), 4 float4 per thread
    #pragma unroll
    for (int i = 0; i < 4; i++) {
        int idx = t + i * 256;          // 1024 float4 total
        int row = idx >> 5, c4 = idx & 31;
        float4 v = *(float4*)&Cs[row][c4 * 4];
        int n = bn * 128 + c4 * 4;
        float4 bb = *(const float4*)&bias[n];
        v.x += bb.x; v.y += bb.y; v.z += bb.z; v.w += bb.w;
        v.x = v.x >= 0.f ? v.x : 0.01f * v.x;
        v.y = v.y >= 0.f ? v.y : 0.01f * v.y;
        v.z = v.z >= 0.f ? v.z : 0.01f * v.z;
        v.w = v.w >= 0.f ? v.w : 0.01f * v.w;
        size_t gi = (size_t)(bm * 32 + row) * DIM + n;
        if (RES) {
            float4 f = *(const float4*)&resid[gi];
            v.x += f.x; v.y += f.y; v.z += f.z; v.w += f.w;
        }
        *(float4*)&C[gi] = v;
    }
}

// ---------------- aggregation: h[d] = 0.5*(meanA(d) + meanB(d)) -------------
// block = 256 threads = 4 dst rows; 64 threads per row, float4 lanes.
__global__ void agg2_kernel(const float* __restrict__ WhA, const int* __restrict__ offA,
                            const int* __restrict__ eA,
                            const float* __restrict__ WhB, const int* __restrict__ offB,
                            const int* __restrict__ eB,
                            float* __restrict__ h, int n) {
    int d = blockIdx.x * 4 + (threadIdx.x >> 6);
    int c = threadIdx.x & 63;
    if (d >= n) return;

    const float4* A4 = (const float4*)WhA;
    const float4* B4 = (const float4*)WhB;

    float4 acc = make_float4(0.f, 0.f, 0.f, 0.f);
    int s0 = offA[d], s1 = offA[d + 1];
    for (int j = s0; j < s1; j++) {
        int s = __ldg(&eA[j]);
        float4 v = __ldg(&A4[(size_t)s * 64 + c]);
        acc.x += v.x; acc.y += v.y; acc.z += v.z; acc.w += v.w;
    }
    float invA = 0.5f / (float)max(s1 - s0, 1);
    float4 r = make_float4(acc.x * invA, acc.y * invA, acc.z * invA, acc.w * invA);

    acc = make_float4(0.f, 0.f, 0.f, 0.f);
    s0 = offB[d]; s1 = offB[d + 1];
    for (int j = s0; j < s1; j++) {
        int s = __ldg(&eB[j]);
        float4 v = __ldg(&B4[(size_t)s * 64 + c]);
        acc.x += v.x; acc.y += v.y; acc.z += v.z; acc.w += v.w;
    }
    float invB = 0.5f / (float)max(s1 - s0, 1);
    r.x += acc.x * invB; r.y += acc.y * invB; r.z += acc.z * invB; r.w += acc.w * invB;

    ((float4*)h)[(size_t)d * 64 + c] = r;
}

// ---------------- launch -----------------------------------------------------
extern "C" void kernel_launch(void* const* d_in, const int* in_sizes, int n_in,
                              void* d_out, int out_size) {
    const float* feat_table = (const float*)d_in[0];
    const float* feat_col   = (const float*)d_in[1];
    const float* W_t2c = (const float*)d_in[2];  const float* b_t2c = (const float*)d_in[3];
    const float* W_c2t = (const float*)d_in[4];  const float* b_c2t = (const float*)d_in[5];
    const float* W_c2c = (const float*)d_in[6];  const float* b_c2c = (const float*)d_in[7];
    const float* W_t2t = (const float*)d_in[8];  const float* b_t2t = (const float*)d_in[9];
    const float* W_h   = (const float*)d_in[10]; const float* b_h   = (const float*)d_in[11];
    const int* src_t2c = (const int*)d_in[12]; const int* dst_t2c = (const int*)d_in[13];
    const int* src_c2t = (const int*)d_in[14]; const int* dst_c2t = (const int*)d_in[15];
    const int* src_c2c = (const int*)d_in[16]; const int* dst_c2c = (const int*)d_in[17];
    const int* src_t2t = (const int*)d_in[18]; const int* dst_t2t = (const int*)d_in[19];
    float* out = (float*)d_out;

    float *Wh_t2c, *Wh_c2t, *Wh_c2c, *Wh_t2t, *h_tab, *h_col;
    int *cnt_t2c, *off_t2c, *pos_t2c, *e_t2c;
    int *cnt_c2t, *off_c2t, *pos_c2t, *e_c2t;
    int *cnt_c2c, *off_c2c, *pos_c2c, *e_c2c;
    int *cnt_t2t, *off_t2t, *pos_t2t, *e_t2t;
    cudaGetSymbolAddress((void**)&Wh_t2c, g_Wh_t2c);
    cudaGetSymbolAddress((void**)&Wh_c2t, g_Wh_c2t);
    cudaGetSymbolAddress((void**)&Wh_c2c, g_Wh_c2c);
    cudaGetSymbolAddress((void**)&Wh_t2t, g_Wh_t2t);
    cudaGetSymbolAddress((void**)&h_tab, g_h_tab);
    cudaGetSymbolAddress((void**)&h_col, g_h_col);
    cudaGetSymbolAddress((void**)&cnt_t2c, g_cnt_t2c); cudaGetSymbolAddress((void**)&off_t2c, g_off_t2c);
    cudaGetSymbolAddress((void**)&pos_t2c, g_pos_t2c); cudaGetSymbolAddress((void**)&e_t2c, g_e_t2c);
    cudaGetSymbolAddress((void**)&cnt_c2t, g_cnt_c2t); cudaGetSymbolAddress((void**)&off_c2t, g_off_c2t);
    cudaGetSymbolAddress((void**)&pos_c2t, g_pos_c2t); cudaGetSymbolAddress((void**)&e_c2t, g_e_c2t);
    cudaGetSymbolAddress((void**)&cnt_c2c, g_cnt_c2c); cudaGetSymbolAddress((void**)&off_c2c, g_off_c2c);
    cudaGetSymbolAddress((void**)&pos_c2c, g_pos_c2c); cudaGetSymbolAddress((void**)&e_c2c, g_e_c2c);
    cudaGetSymbolAddress((void**)&cnt_t2t, g_cnt_t2t); cudaGetSymbolAddress((void**)&off_t2t, g_off_t2t);
    cudaGetSymbolAddress((void**)&pos_t2t, g_pos_t2t); cudaGetSymbolAddress((void**)&e_t2t, g_e_t2t);

    const int Et2c = in_sizes[12], Ec2t = in_sizes[14], Ec2c = in_sizes[16], Et2t = in_sizes[18];

    // 1) zero histograms
    cudaMemsetAsync(cnt_t2c, 0, NC * sizeof(int), 0);
    cudaMemsetAsync(cnt_c2t, 0, NT * sizeof(int), 0);
    cudaMemsetAsync(cnt_c2c, 0, NC * sizeof(int), 0);
    cudaMemsetAsync(cnt_t2t, 0, NT * sizeof(int), 0);

    // 2) histograms
    hist_kernel<<<(Et2c + 255) / 256, 256>>>(dst_t2c, cnt_t2c, Et2c);
    hist_kernel<<<(Ec2t + 255) / 256, 256>>>(dst_c2t, cnt_c2t, Ec2t);
    hist_kernel<<<(Ec2c + 255) / 256, 256>>>(dst_c2c, cnt_c2c, Ec2c);
    hist_kernel<<<(Et2t + 255) / 256, 256>>>(dst_t2t, cnt_t2t, Et2t);

    // 3) exclusive scans
    exscan_kernel<<<1, 1024>>>(cnt_t2c, off_t2c, pos_t2c, NC);
    exscan_kernel<<<1, 1024>>>(cnt_c2t, off_c2t, pos_c2t, NT);
    exscan_kernel<<<1, 1024>>>(cnt_c2c, off_c2c, pos_c2c, NC);
    exscan_kernel<<<1, 1024>>>(cnt_t2t, off_t2t, pos_t2t, NT);

    // 4) CSR edge-source lists
    build_kernel<<<(Et2c + 255) / 256, 256>>>(src_t2c, dst_t2c, pos_t2c, e_t2c, Et2c);
    build_kernel<<<(Ec2t + 255) / 256, 256>>>(src_c2t, dst_c2t, pos_c2t, e_c2t, Ec2t);
    build_kernel<<<(Ec2c + 255) / 256, 256>>>(src_c2c, dst_c2c, pos_c2c, e_c2c, Ec2c);
    build_kernel<<<(Et2t + 255) / 256, 256>>>(src_t2t, dst_t2t, pos_t2t, e_t2t, Et2t);

    // 5) per-etype GEMM + lrelu
    gemm_lrelu_kernel<false><<<dim3(NT / 32, 2), 256>>>(feat_table, W_t2c, b_t2c, nullptr, Wh_t2c);
    gemm_lrelu_kernel<false><<<dim3(NC / 32, 2), 256>>>(feat_col,   W_c2t, b_c2t, nullptr, Wh_c2t);
    gemm_lrelu_kernel<false><<<dim3(NC / 32, 2), 256>>>(feat_col,   W_c2c, b_c2c, nullptr, Wh_c2c);
    gemm_lrelu_kernel<false><<<dim3(NT / 32, 2), 256>>>(feat_table, W_t2t, b_t2t, nullptr, Wh_t2t);

    // 6) mean aggregation + cross-etype mean
    agg2_kernel<<<NT / 4, 256>>>(Wh_c2t, off_c2t, e_c2t, Wh_t2t, off_t2t, e_t2t, h_tab, NT);
    agg2_kernel<<<NC / 4, 256>>>(Wh_t2c, off_t2c, e_t2c, Wh_c2c, off_c2c, e_c2c, h_col, NC);

    // 7) final GEMM + lrelu + residual
    gemm_lrelu_kernel<true><<<dim3(NT / 32, 2), 256>>>(h_tab, W_h, b_h, feat_table, out);
    gemm_lrelu_kernel<true><<<dim3(NC / 32, 2), 256>>>(h_col, W_h, b_h, feat_col, out + (size_t)NT * DIM);
}

// round 2
// speedup vs baseline: 1.2840x; 1.2840x over previous
#include <cuda_runtime.h>
#include <mma.h>

using namespace nvcuda;

#define NT 20000
#define NC 80000
#define DIM 256
#define E_T2C 320000
#define E_C2T 320000
#define E_C2C 640000
#define E_T2T 160000

// ---------------- scratch (device globals; no allocations allowed) ----------
__device__ float g_Wh_t2c[(size_t)NT * DIM];
__device__ float g_Wh_c2t[(size_t)NC * DIM];
__device__ float g_Wh_c2c[(size_t)NC * DIM];
__device__ float g_Wh_t2t[(size_t)NT * DIM];
__device__ float g_h_tab[(size_t)NT * DIM];
__device__ float g_h_col[(size_t)NC * DIM];

__device__ int g_cnt_t2c[NC];     __device__ int g_off_t2c[NC + 1]; __device__ int g_pos_t2c[NC]; __device__ int g_e_t2c[E_T2C];
__device__ int g_cnt_c2t[NT];     __device__ int g_off_c2t[NT + 1]; __device__ int g_pos_c2t[NT]; __device__ int g_e_c2t[E_C2T];
__device__ int g_cnt_c2c[NC];     __device__ int g_off_c2c[NC + 1]; __device__ int g_pos_c2c[NC]; __device__ int g_e_c2c[E_C2C];
__device__ int g_cnt_t2t[NT];     __device__ int g_off_t2t[NT + 1]; __device__ int g_pos_t2t[NT]; __device__ int g_e_t2t[E_T2T];

// ---------------- small helpers ---------------------------------------------
__global__ void hist_kernel(const int* __restrict__ dst, int* __restrict__ cnt, int E) {
    int i = blockIdx.x * blockDim.x + threadIdx.x;
    if (i < E) atomicAdd(&cnt[dst[i]], 1);
}

// ONE kernel, 4 blocks (one per etype). Per block: segment-sum + shuffle block
// scan (3 barriers total) instead of ~1600 barrier waits of the old version.
__global__ void exscan4_kernel(int* c0, int* o0, int* p0, int n0,
                               int* c1, int* o1, int* p1, int n1,
                               int* c2, int* o2, int* p2, int n2,
                               int* c3, int* o3, int* p3, int n3) {
    int* cnt; int* off; int* pos; int n;
    switch (blockIdx.x) {
        case 0: cnt = c0; off = o0; pos = p0; n = n0; break;
        case 1: cnt = c1; off = o1; pos = p1; n = n1; break;
        case 2: cnt = c2; off = o2; pos = p2; n = n2; break;
        default: cnt = c3; off = o3; pos = p3; n = n3; break;
    }
    const int tid = threadIdx.x;           // 1024 threads
    const int lane = tid & 31, warp = tid >> 5;
    const int seg = (n + 1023) / 1024;
    const int s0 = min(tid * seg, n), s1 = min(s0 + seg, n);

    int sum = 0;
    for (int i = s0; i < s1; i++) sum += cnt[i];

    // warp inclusive scan
    int incl = sum;
    #pragma unroll
    for (int ofs = 1; ofs < 32; ofs <<= 1) {
        int v = __shfl_up_sync(0xffffffffu, incl, ofs);
        if (lane >= ofs) incl += v;
    }
    __shared__ int wsum[32];
    __shared__ int woff[32];
    __shared__ int total;
    if (lane == 31) wsum[warp] = incl;
    __syncthreads();
    if (warp == 0) {
        int v = wsum[lane];
        int wi = v;
        #pragma unroll
        for (int ofs = 1; ofs < 32; ofs <<= 1) {
            int t = __shfl_up_sync(0xffffffffu, wi, ofs);
            if (lane >= ofs) wi += t;
        }
        woff[lane] = wi - v;               // exclusive warp offsets
        if (lane == 31) total = wi;
    }
    __syncthreads();

    int run = woff[warp] + (incl - sum);   // exclusive prefix of this thread
    for (int i = s0; i < s1; i++) {
        off[i] = run; pos[i] = run;
        run += cnt[i];
    }
    if (tid == 0) off[n] = total;
}

__global__ void build_kernel(const int* __restrict__ src, const int* __restrict__ dst,
                             int* __restrict__ pos, int* __restrict__ eidx, int E) {
    int i = blockIdx.x * blockDim.x + threadIdx.x;
    if (i < E) {
        int slot = atomicAdd(&pos[dst[i]], 1);
        eidx[slot] = src[i];
    }
}

// ---------------- GEMM: C = lrelu(A @ W^T + b) (+ residual) -----------------
// A: [M,256] row-major, W: [256,256] row-major. BLOCK 128x128, 256 threads,
// warp tile 32x64 = 8 independent tf32 wmma 16x16x8 accumulators (high ILP).
// grid (ceil(M/128), 2).
template <bool RES>
__global__ __launch_bounds__(256, 2)
void gemm_lrelu_kernel(const float* __restrict__ A, const float* __restrict__ W,
                       const float* __restrict__ bias, const float* __restrict__ resid,
                       float* __restrict__ C, int M) {
    const int bm = blockIdx.x, bn = blockIdx.y;
    __shared__ __align__(16) char smem_raw[36864];
    float (*As)[36] = (float(*)[36])smem_raw;                 // [128][36]
    float (*Bs)[36] = (float(*)[36])(smem_raw + 18432);       // [128][36]
    float (*Cs)[32][68] = (float(*)[32][68])smem_raw;         // [4][32][68] (reuse)

    const int t = threadIdx.x;
    const int wid = t >> 5;
    const int wm = wid >> 1;      // 0..3 (row block of 32)
    const int wn = wid & 1;       // 0..1 (col block of 64)

    wmma::fragment<wmma::accumulator, 16, 16, 8, float> acc[2][4];
    #pragma unroll
    for (int i = 0; i < 2; i++)
        #pragma unroll
        for (int j = 0; j < 4; j++) wmma::fill_fragment(acc[i][j], 0.0f);

    for (int kb = 0; kb < 8; kb++) {
        // A tile 128x32 = 1024 float4, 4 per thread (guarded by M)
        #pragma unroll
        for (int i = 0; i < 4; i++) {
            int idx = t + i * 256;
            int row = idx >> 3, c4 = idx & 7;
            int grow = bm * 128 + row;
            float4 v = make_float4(0.f, 0.f, 0.f, 0.f);
            if (grow < M)
                v = *(const float4*)&A[(size_t)grow * DIM + kb * 32 + c4 * 4];
            *(float4*)&As[row][c4 * 4] = v;
        }
        // B tile: W rows are N dim. 128x32 = 1024 float4, 4 per thread
        #pragma unroll
        for (int i = 0; i < 4; i++) {
            int idx = t + i * 256;
            int nrow = idx >> 3, c4 = idx & 7;
            *(float4*)&Bs[nrow][c4 * 4] =
                *(const float4*)&W[(size_t)(bn * 128 + nrow) * DIM + kb * 32 + c4 * 4];
        }
        __syncthreads();

        #pragma unroll
        for (int kk = 0; kk < 4; kk++) {
            wmma::fragment<wmma::matrix_a, 16, 16, 8, wmma::precision::tf32, wmma::row_major> a[2];
            wmma::fragment<wmma::matrix_b, 16, 16, 8, wmma::precision::tf32, wmma::col_major> b[4];
            #pragma unroll
            for (int i = 0; i < 2; i++) {
                wmma::load_matrix_sync(a[i], &As[wm * 32 + i * 16][kk * 8], 36);
                #pragma unroll
                for (int e = 0; e < a[i].num_elements; e++) a[i].x[e] = wmma::__float_to_tf32(a[i].x[e]);
            }
            #pragma unroll
            for (int j = 0; j < 4; j++) {
                wmma::load_matrix_sync(b[j], &Bs[wn * 64 + j * 16][kk * 8], 36);
                #pragma unroll
                for (int e = 0; e < b[j].num_elements; e++) b[j].x[e] = wmma::__float_to_tf32(b[j].x[e]);
            }
            #pragma unroll
            for (int i = 0; i < 2; i++)
                #pragma unroll
                for (int j = 0; j < 4; j++)
                    wmma::mma_sync(acc[i][j], a[i], b[j], acc[i][j]);
        }
        __syncthreads();
    }

    // Epilogue in two warp-waves through reused smem.
    #pragma unroll
    for (int w = 0; w < 2; w++) {
        if ((wid >> 2) == w) {
            int slot = wid & 3;
            #pragma unroll
            for (int i = 0; i < 2; i++)
                #pragma unroll
                for (int j = 0; j < 4; j++)
                    wmma::store_matrix_sync(&Cs[slot][i * 16][j * 16], acc[i][j], 68,
                                            wmma::mem_row_major);
        }
        __syncthreads();
        // write out wave's 4 slots: 4*32*16 float4 = 2048, 8 per thread
        #pragma unroll
        for (int i = 0; i < 8; i++) {
            int idx = t + i * 256;
            int slot = idx >> 9;
            int within = idx & 511;
            int row = within >> 4, c4 = within & 15;
            int grow = bm * 128 + (w * 2 + (slot >> 1)) * 32 + row;
            if (grow >= M) continue;
            int col = bn * 128 + (slot & 1) * 64 + c4 * 4;
            float4 v = *(float4*)&Cs[slot][row][c4 * 4];
            float4 bb = *(const float4*)&bias[col];
            v.x += bb.x; v.y += bb.y; v.z += bb.z; v.w += bb.w;
            v.x = v.x >= 0.f ? v.x : 0.01f * v.x;
            v.y = v.y >= 0.f ? v.y : 0.01f * v.y;
            v.z = v.z >= 0.f ? v.z : 0.01f * v.z;
            v.w = v.w >= 0.f ? v.w : 0.01f * v.w;
            size_t gi = (size_t)grow * DIM + col;
            if (RES) {
                float4 f = *(const float4*)&resid[gi];
                v.x += f.x; v.y += f.y; v.z += f.z; v.w += f.w;
            }
            *(float4*)&C[gi] = v;
        }
        __syncthreads();
    }
}

// ---------------- aggregation: h[d] = 0.5*(meanA(d) + meanB(d)) -------------
__global__ void agg2_kernel(const float* __restrict__ WhA, const int* __restrict__ offA,
                            const int* __restrict__ eA,
                            const float* __restrict__ WhB, const int* __restrict__ offB,
                            const int* __restrict__ eB,
                            float* __restrict__ h, int n) {
    int d = blockIdx.x * 4 + (threadIdx.x >> 6);
    int c = threadIdx.x & 63;
    if (d >= n) return;

    const float4* A4 = (const float4*)WhA;
    const float4* B4 = (const float4*)WhB;

    float4 acc = make_float4(0.f, 0.f, 0.f, 0.f);
    int s0 = offA[d], s1 = offA[d + 1];
    for (int j = s0; j < s1; j++) {
        int s = __ldg(&eA[j]);
        float4 v = __ldg(&A4[(size_t)s * 64 + c]);
        acc.x += v.x; acc.y += v.y; acc.z += v.z; acc.w += v.w;
    }
    float invA = 0.5f / (float)max(s1 - s0, 1);
    float4 r = make_float4(acc.x * invA, acc.y * invA, acc.z * invA, acc.w * invA);

    acc = make_float4(0.f, 0.f, 0.f, 0.f);
    s0 = offB[d]; s1 = offB[d + 1];
    for (int j = s0; j < s1; j++) {
        int s = __ldg(&eB[j]);
        float4 v = __ldg(&B4[(size_t)s * 64 + c]);
        acc.x += v.x; acc.y += v.y; acc.z += v.z; acc.w += v.w;
    }
    float invB = 0.5f / (float)max(s1 - s0, 1);
    r.x += acc.x * invB; r.y += acc.y * invB; r.z += acc.z * invB; r.w += acc.w * invB;

    ((float4*)h)[(size_t)d * 64 + c] = r;
}

// ---------------- launch -----------------------------------------------------
extern "C" void kernel_launch(void* const* d_in, const int* in_sizes, int n_in,
                              void* d_out, int out_size) {
    const float* feat_table = (const float*)d_in[0];
    const float* feat_col   = (const float*)d_in[1];
    const float* W_t2c = (const float*)d_in[2];  const float* b_t2c = (const float*)d_in[3];
    const float* W_c2t = (const float*)d_in[4];  const float* b_c2t = (const float*)d_in[5];
    const float* W_c2c = (const float*)d_in[6];  const float* b_c2c = (const float*)d_in[7];
    const float* W_t2t = (const float*)d_in[8];  const float* b_t2t = (const float*)d_in[9];
    const float* W_h   = (const float*)d_in[10]; const float* b_h   = (const float*)d_in[11];
    const int* src_t2c = (const int*)d_in[12]; const int* dst_t2c = (const int*)d_in[13];
    const int* src_c2t = (const int*)d_in[14]; const int* dst_c2t = (const int*)d_in[15];
    const int* src_c2c = (const int*)d_in[16]; const int* dst_c2c = (const int*)d_in[17];
    const int* src_t2t = (const int*)d_in[18]; const int* dst_t2t = (const int*)d_in[19];
    float* out = (float*)d_out;

    float *Wh_t2c, *Wh_c2t, *Wh_c2c, *Wh_t2t, *h_tab, *h_col;
    int *cnt_t2c, *off_t2c, *pos_t2c, *e_t2c;
    int *cnt_c2t, *off_c2t, *pos_c2t, *e_c2t;
    int *cnt_c2c, *off_c2c, *pos_c2c, *e_c2c;
    int *cnt_t2t, *off_t2t, *pos_t2t, *e_t2t;
    cudaGetSymbolAddress((void**)&Wh_t2c, g_Wh_t2c);
    cudaGetSymbolAddress((void**)&Wh_c2t, g_Wh_c2t);
    cudaGetSymbolAddress((void**)&Wh_c2c, g_Wh_c2c);
    cudaGetSymbolAddress((void**)&Wh_t2t, g_Wh_t2t);
    cudaGetSymbolAddress((void**)&h_tab, g_h_tab);
    cudaGetSymbolAddress((void**)&h_col, g_h_col);
    cudaGetSymbolAddress((void**)&cnt_t2c, g_cnt_t2c); cudaGetSymbolAddress((void**)&off_t2c, g_off_t2c);
    cudaGetSymbolAddress((void**)&pos_t2c, g_pos_t2c); cudaGetSymbolAddress((void**)&e_t2c, g_e_t2c);
    cudaGetSymbolAddress((void**)&cnt_c2t, g_cnt_c2t); cudaGetSymbolAddress((void**)&off_c2t, g_off_c2t);
    cudaGetSymbolAddress((void**)&pos_c2t, g_pos_c2t); cudaGetSymbolAddress((void**)&e_c2t, g_e_c2t);
    cudaGetSymbolAddress((void**)&cnt_c2c, g_cnt_c2c); cudaGetSymbolAddress((void**)&off_c2c, g_off_c2c);
    cudaGetSymbolAddress((void**)&pos_c2c, g_pos_c2c); cudaGetSymbolAddress((void**)&e_c2c, g_e_c2c);
    cudaGetSymbolAddress((void**)&cnt_t2t, g_cnt_t2t); cudaGetSymbolAddress((void**)&off_t2t, g_off_t2t);
    cudaGetSymbolAddress((void**)&pos_t2t, g_pos_t2t); cudaGetSymbolAddress((void**)&e_t2t, g_e_t2t);

    const int Et2c = in_sizes[12], Ec2t = in_sizes[14], Ec2c = in_sizes[16], Et2t = in_sizes[18];

    // 1) zero histograms
    cudaMemsetAsync(cnt_t2c, 0, NC * sizeof(int), 0);
    cudaMemsetAsync(cnt_c2t, 0, NT * sizeof(int), 0);
    cudaMemsetAsync(cnt_c2c, 0, NC * sizeof(int), 0);
    cudaMemsetAsync(cnt_t2t, 0, NT * sizeof(int), 0);

    // 2) histograms
    hist_kernel<<<(Et2c + 255) / 256, 256>>>(dst_t2c, cnt_t2c, Et2c);
    hist_kernel<<<(Ec2t + 255) / 256, 256>>>(dst_c2t, cnt_c2t, Ec2t);
    hist_kernel<<<(Ec2c + 255) / 256, 256>>>(dst_c2c, cnt_c2c, Ec2c);
    hist_kernel<<<(Et2t + 255) / 256, 256>>>(dst_t2t, cnt_t2t, Et2t);

    // 3) all 4 exclusive scans in ONE launch
    exscan4_kernel<<<4, 1024>>>(cnt_t2c, off_t2c, pos_t2c, NC,
                                cnt_c2t, off_c2t, pos_c2t, NT,
                                cnt_c2c, off_c2c, pos_c2c, NC,
                                cnt_t2t, off_t2t, pos_t2t, NT);

    // 4) CSR edge-source lists
    build_kernel<<<(Et2c + 255) / 256, 256>>>(src_t2c, dst_t2c, pos_t2c, e_t2c, Et2c);
    build_kernel<<<(Ec2t + 255) / 256, 256>>>(src_c2t, dst_c2t, pos_c2t, e_c2t, Ec2t);
    build_kernel<<<(Ec2c + 255) / 256, 256>>>(src_c2c, dst_c2c, pos_c2c, e_c2c, Ec2c);
    build_kernel<<<(Et2t + 255) / 256, 256>>>(src_t2t, dst_t2t, pos_t2t, e_t2t, Et2t);

    // 5) per-etype GEMM + lrelu
    const int gT = (NT + 127) / 128, gC = (NC + 127) / 128;
    gemm_lrelu_kernel<false><<<dim3(gT, 2), 256>>>(feat_table, W_t2c, b_t2c, nullptr, Wh_t2c, NT);
    gemm_lrelu_kernel<false><<<dim3(gC, 2), 256>>>(feat_col,   W_c2t, b_c2t, nullptr, Wh_c2t, NC);
    gemm_lrelu_kernel<false><<<dim3(gC, 2), 256>>>(feat_col,   W_c2c, b_c2c, nullptr, Wh_c2c, NC);
    gemm_lrelu_kernel<false><<<dim3(gT, 2), 256>>>(feat_table, W_t2t, b_t2t, nullptr, Wh_t2t, NT);

    // 6) mean aggregation + cross-etype mean
    agg2_kernel<<<NT / 4, 256>>>(Wh_c2t, off_c2t, e_c2t, Wh_t2t, off_t2t, e_t2t, h_tab, NT);
    agg2_kernel<<<NC / 4, 256>>>(Wh_t2c, off_t2c, e_t2c, Wh_c2c, off_c2c, e_c2c, h_col, NC);

    // 7) final GEMM + lrelu + residual
    gemm_lrelu_kernel<true><<<dim3(gT, 2), 256>>>(h_tab, W_h, b_h, feat_table, out, NT);
    gemm_lrelu_kernel<true><<<dim3(gC, 2), 256>>>(h_col, W_h, b_h, feat_col, out + (size_t)NT * DIM, NC);
}

// round 4
// speedup vs baseline: 1.4370x; 1.1192x over previous
#include <cuda_runtime.h>
#include <mma.h>
#include <cstdint>

using namespace nvcuda;

#define NT 20000
#define NC 80000
#define DIM 256
#define E_T2C 320000
#define E_C2T 320000
#define E_C2C 640000
#define E_T2T 160000

// ---------------- scratch (device globals; no allocations allowed) ----------
__device__ float g_Wh_t2c[(size_t)NT * DIM];
__device__ float g_Wh_c2t[(size_t)NC * DIM];
__device__ float g_Wh_c2c[(size_t)NC * DIM];
__device__ float g_Wh_t2t[(size_t)NT * DIM];
__device__ float g_h[(size_t)(NT + NC) * DIM];

// combined count array: [t2c: NC][c2t: NT][c2c: NC][t2t: NT]
#define CNT_T2C 0
#define CNT_C2T NC
#define CNT_C2C (NC + NT)
#define CNT_T2T (NC + NT + NC)
#define CNT_TOTAL (2 * NC + 2 * NT)
__device__ int g_cnt[CNT_TOTAL];
__device__ int g_off_t2c[NC + 1]; __device__ int g_pos_t2c[NC]; __device__ int g_e_t2c[E_T2C];
__device__ int g_off_c2t[NT + 1]; __device__ int g_pos_c2t[NT]; __device__ int g_e_c2t[E_C2T];
__device__ int g_off_c2c[NC + 1]; __device__ int g_pos_c2c[NC]; __device__ int g_e_c2c[E_C2C];
__device__ int g_off_t2t[NT + 1]; __device__ int g_pos_t2t[NT]; __device__ int g_e_t2t[E_T2T];

// ---------------- helpers ----------------------------------------------------
__device__ __forceinline__ uint32_t smem_u32(const void* p) {
    uint32_t a;
    asm("{ .reg .u64 t; cvta.to.shared.u64 t, %1; cvt.u32.u64 %0, t; }" : "=r"(a) : "l"(p));
    return a;
}
#define CP_ASYNC16(dst, src) \
    asm volatile("cp.async.cg.shared.global [%0], [%1], 16;" :: "r"(dst), "l"(src))
#define CP_COMMIT() asm volatile("cp.async.commit_group;" ::: "memory")
#define CP_WAIT1() asm volatile("cp.async.wait_group 1;" ::: "memory")
#define CP_WAIT0() asm volatile("cp.async.wait_group 0;" ::: "memory")

// fused histogram over 4 edge lists
__global__ void hist4_kernel(const int* __restrict__ d0, const int* __restrict__ d1,
                             const int* __restrict__ d2, const int* __restrict__ d3,
                             int* __restrict__ cnt,
                             int E0, int E1, int E2, int E3) {
    int i = blockIdx.x * blockDim.x + threadIdx.x;
    if (i < E0) { atomicAdd(&cnt[CNT_T2C + d0[i]], 1); return; }
    i -= E0;
    if (i < E1) { atomicAdd(&cnt[CNT_C2T + d1[i]], 1); return; }
    i -= E1;
    if (i < E2) { atomicAdd(&cnt[CNT_C2C + d2[i]], 1); return; }
    i -= E2;
    if (i < E3) { atomicAdd(&cnt[CNT_T2T + d3[i]], 1); }
}

__global__ void exscan4_kernel(const int* __restrict__ cntbase,
                               int* o0, int* p0, int* o1, int* p1,
                               int* o2, int* p2, int* o3, int* p3) {
    const int* cnt; int* off; int* pos; int n;
    switch (blockIdx.x) {
        case 0: cnt = cntbase + CNT_T2C; off = o0; pos = p0; n = NC; break;
        case 1: cnt = cntbase + CNT_C2T; off = o1; pos = p1; n = NT; break;
        case 2: cnt = cntbase + CNT_C2C; off = o2; pos = p2; n = NC; break;
        default: cnt = cntbase + CNT_T2T; off = o3; pos = p3; n = NT; break;
    }
    const int tid = threadIdx.x;
    const int lane = tid & 31, warp = tid >> 5;
    const int seg = (n + 1023) / 1024;
    const int s0 = min(tid * seg, n), s1 = min(s0 + seg, n);

    int sum = 0;
    for (int i = s0; i < s1; i++) sum += cnt[i];

    int incl = sum;
    #pragma unroll
    for (int ofs = 1; ofs < 32; ofs <<= 1) {
        int v = __shfl_up_sync(0xffffffffu, incl, ofs);
        if (lane >= ofs) incl += v;
    }
    __shared__ int wsum[32];
    __shared__ int woff[32];
    __shared__ int total;
    if (lane == 31) wsum[warp] = incl;
    __syncthreads();
    if (warp == 0) {
        int v = wsum[lane];
        int wi = v;
        #pragma unroll
        for (int ofs = 1; ofs < 32; ofs <<= 1) {
            int t2 = __shfl_up_sync(0xffffffffu, wi, ofs);
            if (lane >= ofs) wi += t2;
        }
        woff[lane] = wi - v;
        if (lane == 31) total = wi;
    }
    __syncthreads();

    int run = woff[warp] + (incl - sum);
    for (int i = s0; i < s1; i++) {
        off[i] = run; pos[i] = run;
        run += cnt[i];
    }
    if (tid == 0) off[n] = total;
}

// fused CSR build over 4 edge lists
__global__ void build4_kernel(const int* __restrict__ s0, const int* __restrict__ d0, int* p0, int* e0,
                              const int* __restrict__ s1, const int* __restrict__ d1, int* p1, int* e1,
                              const int* __restrict__ s2, const int* __restrict__ d2, int* p2, int* e2,
                              const int* __restrict__ s3, const int* __restrict__ d3, int* p3, int* e3,
                              int E0, int E1, int E2, int E3) {
    int i = blockIdx.x * blockDim.x + threadIdx.x;
    if (i < E0) { int sl = atomicAdd(&p0[d0[i]], 1); e0[sl] = s0[i]; return; }
    i -= E0;
    if (i < E1) { int sl = atomicAdd(&p1[d1[i]], 1); e1[sl] = s1[i]; return; }
    i -= E1;
    if (i < E2) { int sl = atomicAdd(&p2[d2[i]], 1); e2[sl] = s2[i]; return; }
    i -= E2;
    if (i < E3) { int sl = atomicAdd(&p3[d3[i]], 1); e3[sl] = s3[i]; }
}

// ---------------- GEMM: C = lrelu(A @ W^T + b) (+ residual) -----------------
// 128x128 tile, 256 thr, warp tile 32x64 (8 tf32 wmma accs), cp.async 2-stage.
// dynamic smem: stage0 A[128][36] B[128][36], stage1 same = 73728 B.
#define ST_BYTES 18432
#define GEMM_SMEM (4 * ST_BYTES)

template <bool RES>
__global__ __launch_bounds__(256, 2)
void gemm_lrelu_kernel(const float* __restrict__ A, const float* __restrict__ W,
                       const float* __restrict__ bias,
                       const float* __restrict__ resA, const float* __restrict__ resB,
                       int splitM, float* __restrict__ C, int M) {
    extern __shared__ __align__(16) char smem[];
    const int bm = blockIdx.x, bn = blockIdx.y;
    const int t = threadIdx.x;
    const int wid = t >> 5;
    const int wm = wid >> 1;      // 0..3
    const int wn = wid & 1;       // 0..1
    const uint32_t sb = smem_u32(smem);

    wmma::fragment<wmma::accumulator, 16, 16, 8, float> acc[2][4];
    #pragma unroll
    for (int i = 0; i < 2; i++)
        #pragma unroll
        for (int j = 0; j < 4; j++) wmma::fill_fragment(acc[i][j], 0.0f);

    // per-thread load coords (A/B tiles: 128x32 = 1024 f4 each, 4 per thread)
    const int lrow = t >> 3, lc4 = t & 7;   // base: rows lrow, lrow+32, +64, +96

    auto prefetch = [&](int stage, int kb) {
        uint32_t baseA = sb + stage * 2 * ST_BYTES;
        uint32_t baseB = baseA + ST_BYTES;
        #pragma unroll
        for (int i = 0; i < 4; i++) {
            int row = lrow + i * 32;
            int grow = bm * 128 + row;
            if (grow > M - 1) grow = M - 1;
            CP_ASYNC16(baseA + (uint32_t)(row * 36 + lc4 * 4) * 4,
                       A + (size_t)grow * DIM + kb * 32 + lc4 * 4);
        }
        #pragma unroll
        for (int i = 0; i < 4; i++) {
            int row = lrow + i * 32;
            CP_ASYNC16(baseB + (uint32_t)(row * 36 + lc4 * 4) * 4,
                       W + (size_t)(bn * 128 + row) * DIM + kb * 32 + lc4 * 4);
        }
        CP_COMMIT();
    };

    prefetch(0, 0);

    for (int kb = 0; kb < 8; kb++) {
        const int s = kb & 1;
        if (kb < 7) { prefetch(s ^ 1, kb + 1); CP_WAIT1(); }
        else        { CP_WAIT0(); }
        __syncthreads();

        float (*As)[36] = (float(*)[36])(smem + s * 2 * ST_BYTES);
        float (*Bs)[36] = (float(*)[36])(smem + s * 2 * ST_BYTES + ST_BYTES);

        #pragma unroll
        for (int kk = 0; kk < 4; kk++) {
            wmma::fragment<wmma::matrix_a, 16, 16, 8, wmma::precision::tf32, wmma::row_major> a[2];
            wmma::fragment<wmma::matrix_b, 16, 16, 8, wmma::precision::tf32, wmma::col_major> b[4];
            #pragma unroll
            for (int i = 0; i < 2; i++) {
                wmma::load_matrix_sync(a[i], &As[wm * 32 + i * 16][kk * 8], 36);
                #pragma unroll
                for (int e = 0; e < a[i].num_elements; e++) a[i].x[e] = wmma::__float_to_tf32(a[i].x[e]);
            }
            #pragma unroll
            for (int j = 0; j < 4; j++) {
                wmma::load_matrix_sync(b[j], &Bs[wn * 64 + j * 16][kk * 8], 36);
                #pragma unroll
                for (int e = 0; e < b[j].num_elements; e++) b[j].x[e] = wmma::__float_to_tf32(b[j].x[e]);
            }
            #pragma unroll
            for (int i = 0; i < 2; i++)
                #pragma unroll
                for (int j = 0; j < 4; j++)
                    wmma::mma_sync(acc[i][j], a[i], b[j], acc[i][j]);
        }
        __syncthreads();
    }

    // Epilogue via reused smem (Cs [4][32][68] = 34816 B), two warp-waves.
    float (*Cs)[32][68] = (float(*)[32][68])smem;
    #pragma unroll
    for (int w = 0; w < 2; w++) {
        if ((wid >> 2) == w) {
            int slot = wid & 3;
            #pragma unroll
            for (int i = 0; i < 2; i++)
                #pragma unroll
                for (int j = 0; j < 4; j++)
                    wmma::store_matrix_sync(&Cs[slot][i * 16][j * 16], acc[i][j], 68,
                                            wmma::mem_row_major);
        }
        __syncthreads();
        #pragma unroll
        for (int i = 0; i < 8; i++) {
            int idx = t + i * 256;
            int slot = idx >> 9;
            int within = idx & 511;
            int row = within >> 4, c4 = within & 15;
            int grow = bm * 128 + (w * 2 + (slot >> 1)) * 32 + row;
            if (grow >= M) continue;
            int col = bn * 128 + (slot & 1) * 64 + c4 * 4;
            float4 v = *(float4*)&Cs[slot][row][c4 * 4];
            float4 bb = *(const float4*)&bias[col];
            v.x += bb.x; v.y += bb.y; v.z += bb.z; v.w += bb.w;
            v.x = v.x >= 0.f ? v.x : 0.01f * v.x;
            v.y = v.y >= 0.f ? v.y : 0.01f * v.y;
            v.z = v.z >= 0.f ? v.z : 0.01f * v.z;
            v.w = v.w >= 0.f ? v.w : 0.01f * v.w;
            size_t gi = (size_t)grow * DIM + col;
            if (RES) {
                const float* rp = (grow < splitM)
                    ? &resA[(size_t)grow * DIM + col]
                    : &resB[(size_t)(grow - splitM) * DIM + col];
                float4 f = *(const float4*)rp;
                v.x += f.x; v.y += f.y; v.z += f.z; v.w += f.w;
            }
            *(float4*)&C[gi] = v;
        }
        __syncthreads();
    }
}

// ---------------- aggregation: h[d] = 0.5*(meanA(d) + meanB(d)) -------------
__global__ void agg2_kernel(const float* __restrict__ WhA, const int* __restrict__ offA,
                            const int* __restrict__ eA,
                            const float* __restrict__ WhB, const int* __restrict__ offB,
                            const int* __restrict__ eB,
                            float* __restrict__ h, int n) {
    int d = blockIdx.x * 4 + (threadIdx.x >> 6);
    int c = threadIdx.x & 63;
    if (d >= n) return;

    const float4* A4 = (const float4*)WhA;
    const float4* B4 = (const float4*)WhB;

    float4 acc = make_float4(0.f, 0.f, 0.f, 0.f);
    int s0 = offA[d], s1 = offA[d + 1];
    for (int j = s0; j < s1; j++) {
        int s = __ldg(&eA[j]);
        float4 v = __ldg(&A4[(size_t)s * 64 + c]);
        acc.x += v.x; acc.y += v.y; acc.z += v.z; acc.w += v.w;
    }
    float invA = 0.5f / (float)max(s1 - s0, 1);
    float4 r = make_float4(acc.x * invA, acc.y * invA, acc.z * invA, acc.w * invA);

    acc = make_float4(0.f, 0.f, 0.f, 0.f);
    s0 = offB[d]; s1 = offB[d + 1];
    for (int j = s0; j < s1; j++) {
        int s = __ldg(&eB[j]);
        float4 v = __ldg(&B4[(size_t)s * 64 + c]);
        acc.x += v.x; acc.y += v.y; acc.z += v.z; acc.w += v.w;
    }
    float invB = 0.5f / (float)max(s1 - s0, 1);
    r.x += acc.x * invB; r.y += acc.y * invB; r.z += acc.z * invB; r.w += acc.w * invB;

    ((float4*)h)[(size_t)d * 64 + c] = r;
}

// ---------------- launch -----------------------------------------------------
extern "C" void kernel_launch(void* const* d_in, const int* in_sizes, int n_in,
                              void* d_out, int out_size) {
    const float* feat_table = (const float*)d_in[0];
    const float* feat_col   = (const float*)d_in[1];
    const float* W_t2c = (const float*)d_in[2];  const float* b_t2c = (const float*)d_in[3];
    const float* W_c2t = (const float*)d_in[4];  const float* b_c2t = (const float*)d_in[5];
    const float* W_c2c = (const float*)d_in[6];  const float* b_c2c = (const float*)d_in[7];
    const float* W_t2t = (const float*)d_in[8];  const float* b_t2t = (const float*)d_in[9];
    const float* W_h   = (const float*)d_in[10]; const float* b_h   = (const float*)d_in[11];
    const int* src_t2c = (const int*)d_in[12]; const int* dst_t2c = (const int*)d_in[13];
    const int* src_c2t = (const int*)d_in[14]; const int* dst_c2t = (const int*)d_in[15];
    const int* src_c2c = (const int*)d_in[16]; const int* dst_c2c = (const int*)d_in[17];
    const int* src_t2t = (const int*)d_in[18]; const int* dst_t2t = (const int*)d_in[19];
    float* out = (float*)d_out;

    float *Wh_t2c, *Wh_c2t, *Wh_c2c, *Wh_t2t, *h;
    int *cnt;
    int *off_t2c, *pos_t2c, *e_t2c;
    int *off_c2t, *pos_c2t, *e_c2t;
    int *off_c2c, *pos_c2c, *e_c2c;
    int *off_t2t, *pos_t2t, *e_t2t;
    cudaGetSymbolAddress((void**)&Wh_t2c, g_Wh_t2c);
    cudaGetSymbolAddress((void**)&Wh_c2t, g_Wh_c2t);
    cudaGetSymbolAddress((void**)&Wh_c2c, g_Wh_c2c);
    cudaGetSymbolAddress((void**)&Wh_t2t, g_Wh_t2t);
    cudaGetSymbolAddress((void**)&h, g_h);
    cudaGetSymbolAddress((void**)&cnt, g_cnt);
    cudaGetSymbolAddress((void**)&off_t2c, g_off_t2c); cudaGetSymbolAddress((void**)&pos_t2c, g_pos_t2c);
    cudaGetSymbolAddress((void**)&e_t2c, g_e_t2c);
    cudaGetSymbolAddress((void**)&off_c2t, g_off_c2t); cudaGetSymbolAddress((void**)&pos_c2t, g_pos_c2t);
    cudaGetSymbolAddress((void**)&e_c2t, g_e_c2t);
    cudaGetSymbolAddress((void**)&off_c2c, g_off_c2c); cudaGetSymbolAddress((void**)&pos_c2c, g_pos_c2c);
    cudaGetSymbolAddress((void**)&e_c2c, g_e_c2c);
    cudaGetSymbolAddress((void**)&off_t2t, g_off_t2t); cudaGetSymbolAddress((void**)&pos_t2t, g_pos_t2t);
    cudaGetSymbolAddress((void**)&e_t2t, g_e_t2t);

    cudaFuncSetAttribute(gemm_lrelu_kernel<false>, cudaFuncAttributeMaxDynamicSharedMemorySize, GEMM_SMEM);
    cudaFuncSetAttribute(gemm_lrelu_kernel<true>,  cudaFuncAttributeMaxDynamicSharedMemorySize, GEMM_SMEM);

    const int Et2c = in_sizes[12], Ec2t = in_sizes[14], Ec2c = in_sizes[16], Et2t = in_sizes[18];
    const int Eall = Et2c + Ec2t + Ec2c + Et2t;

    cudaMemsetAsync(cnt, 0, CNT_TOTAL * sizeof(int), 0);

    hist4_kernel<<<(Eall + 255) / 256, 256>>>(dst_t2c, dst_c2t, dst_c2c, dst_t2t,
                                              cnt, Et2c, Ec2t, Ec2c, Et2t);

    exscan4_kernel<<<4, 1024>>>(cnt, off_t2c, pos_t2c, off_c2t, pos_c2t,
                                off_c2c, pos_c2c, off_t2t, pos_t2t);

    build4_kernel<<<(Eall + 255) / 256, 256>>>(
        src_t2c, dst_t2c, pos_t2c, e_t2c,
        src_c2t, dst_c2t, pos_c2t, e_c2t,
        src_c2c, dst_c2c, pos_c2c, e_c2c,
        src_t2t, dst_t2t, pos_t2t, e_t2t,
        Et2c, Ec2t, Ec2c, Et2t);

    const int gT = (NT + 127) / 128, gC = (NC + 127) / 128, gAll = (NT + NC + 127) / 128;
    gemm_lrelu_kernel<false><<<dim3(gT, 2), 256, GEMM_SMEM>>>(feat_table, W_t2c, b_t2c, nullptr, nullptr, 0, Wh_t2c, NT);
    gemm_lrelu_kernel<false><<<dim3(gC, 2), 256, GEMM_SMEM>>>(feat_col,   W_c2t, b_c2t, nullptr, nullptr, 0, Wh_c2t, NC);
    gemm_lrelu_kernel<false><<<dim3(gC, 2), 256, GEMM_SMEM>>>(feat_col,   W_c2c, b_c2c, nullptr, nullptr, 0, Wh_c2c, NC);
    gemm_lrelu_kernel<false><<<dim3(gT, 2), 256, GEMM_SMEM>>>(feat_table, W_t2t, b_t2t, nullptr, nullptr, 0, Wh_t2t, NT);

    agg2_kernel<<<NT / 4, 256>>>(Wh_c2t, off_c2t, e_c2t, Wh_t2t, off_t2t, e_t2t, h, NT);
    agg2_kernel<<<NC / 4, 256>>>(Wh_t2c, off_t2c, e_t2c, Wh_c2c, off_c2c, e_c2c, h + (size_t)NT * DIM, NC);

    // fused final GEMM over all 100000 rows, residual split at NT
    gemm_lrelu_kernel<true><<<dim3(gAll, 2), 256, GEMM_SMEM>>>(h, W_h, b_h, feat_table, feat_col, NT, out, NT + NC);
}

// round 5
// speedup vs baseline: 2.6838x; 1.8676x over previous
#include <cuda_runtime.h>
#include <cuda_fp16.h>
#include <mma.h>
#include <cstdint>

using namespace nvcuda;

#define NT 20000
#define NC 80000
#define DIM 256
#define E_T2C 320000
#define E_C2T 320000
#define E_C2C 640000
#define E_T2T 160000

// ---------------- scratch (device globals; no allocations allowed) ----------
__device__ __half g_feat16[(size_t)(NT + NC) * DIM];       // [table | column]
__device__ __half g_W16[5 * DIM * DIM];                    // t2c,c2t,c2c,t2t,h
__device__ __half g_Wh_t2c[(size_t)NC ? (size_t)NT * DIM : 0];
__device__ __half g_Wh_c2t[(size_t)NC * DIM];
__device__ __half g_Wh_c2c[(size_t)NC * DIM];
__device__ __half g_Wh_t2t[(size_t)NT * DIM];
__device__ __half g_h16[(size_t)(NT + NC) * DIM];

#define CNT_T2C 0
#define CNT_C2T NC
#define CNT_C2C (NC + NT)
#define CNT_T2T (NC + NT + NC)
#define CNT_TOTAL (2 * NC + 2 * NT)
__device__ int g_cnt[CNT_TOTAL];
__device__ int g_off_t2c[NC + 1]; __device__ int g_pos_t2c[NC]; __device__ int g_e_t2c[E_T2C];
__device__ int g_off_c2t[NT + 1]; __device__ int g_pos_c2t[NT]; __device__ int g_e_c2t[E_C2T];
__device__ int g_off_c2c[NC + 1]; __device__ int g_pos_c2c[NC]; __device__ int g_e_c2c[E_C2C];
__device__ int g_off_t2t[NT + 1]; __device__ int g_pos_t2t[NT]; __device__ int g_e_t2t[E_T2T];

// ---------------- helpers ----------------------------------------------------
__device__ __forceinline__ uint32_t smem_u32(const void* p) {
    uint32_t a;
    asm("{ .reg .u64 t; cvta.to.shared.u64 t, %1; cvt.u32.u64 %0, t; }" : "=r"(a) : "l"(p));
    return a;
}
#define CP_ASYNC16(dst, src) \
    asm volatile("cp.async.cg.shared.global [%0], [%1], 16;" :: "r"(dst), "l"(src))
#define CP_COMMIT() asm volatile("cp.async.commit_group;" ::: "memory")
#define CP_WAIT1() asm volatile("cp.async.wait_group 1;" ::: "memory")
#define CP_WAIT0() asm volatile("cp.async.wait_group 0;" ::: "memory")

// ---------------- conversion kernels -----------------------------------------
__global__ void cvt_kernel(const float* __restrict__ src, __half* __restrict__ dst, int n4) {
    int i = blockIdx.x * blockDim.x + threadIdx.x;
    if (i >= n4) return;
    float4 v = ((const float4*)src)[i];
    half2* d2 = (half2*)dst;
    d2[2 * i]     = __floats2half2_rn(v.x, v.y);
    d2[2 * i + 1] = __floats2half2_rn(v.z, v.w);
}

__global__ void cvt_w_kernel(const float* __restrict__ w0, const float* __restrict__ w1,
                             const float* __restrict__ w2, const float* __restrict__ w3,
                             const float* __restrict__ w4, __half* __restrict__ dst) {
    int i = blockIdx.x * blockDim.x + threadIdx.x;   // float4 index, 5*16384 total
    if (i >= 5 * 16384) return;
    const float* srcs[5] = {w0, w1, w2, w3, w4};
    const float* s = srcs[i >> 14];
    int j = i & 16383;
    float4 v = ((const float4*)s)[j];
    half2* d2 = (half2*)dst;
    d2[2 * i]     = __floats2half2_rn(v.x, v.y);
    d2[2 * i + 1] = __floats2half2_rn(v.z, v.w);
}

// ---------------- graph preprocessing ----------------------------------------
__global__ void hist4_kernel(const int* __restrict__ d0, const int* __restrict__ d1,
                             const int* __restrict__ d2, const int* __restrict__ d3,
                             int* __restrict__ cnt,
                             int E0, int E1, int E2, int E3) {
    int i = blockIdx.x * blockDim.x + threadIdx.x;
    if (i < E0) { atomicAdd(&cnt[CNT_T2C + d0[i]], 1); return; }
    i -= E0;
    if (i < E1) { atomicAdd(&cnt[CNT_C2T + d1[i]], 1); return; }
    i -= E1;
    if (i < E2) { atomicAdd(&cnt[CNT_C2C + d2[i]], 1); return; }
    i -= E2;
    if (i < E3) { atomicAdd(&cnt[CNT_T2T + d3[i]], 1); }
}

__global__ void exscan4_kernel(const int* __restrict__ cntbase,
                               int* o0, int* p0, int* o1, int* p1,
                               int* o2, int* p2, int* o3, int* p3) {
    const int* cnt; int* off; int* pos; int n;
    switch (blockIdx.x) {
        case 0: cnt = cntbase + CNT_T2C; off = o0; pos = p0; n = NC; break;
        case 1: cnt = cntbase + CNT_C2T; off = o1; pos = p1; n = NT; break;
        case 2: cnt = cntbase + CNT_C2C; off = o2; pos = p2; n = NC; break;
        default: cnt = cntbase + CNT_T2T; off = o3; pos = p3; n = NT; break;
    }
    const int tid = threadIdx.x;
    const int lane = tid & 31, warp = tid >> 5;
    const int seg = (n + 1023) / 1024;
    const int s0 = min(tid * seg, n), s1 = min(s0 + seg, n);

    int sum = 0;
    for (int i = s0; i < s1; i++) sum += cnt[i];

    int incl = sum;
    #pragma unroll
    for (int ofs = 1; ofs < 32; ofs <<= 1) {
        int v = __shfl_up_sync(0xffffffffu, incl, ofs);
        if (lane >= ofs) incl += v;
    }
    __shared__ int wsum[32];
    __shared__ int woff[32];
    __shared__ int total;
    if (lane == 31) wsum[warp] = incl;
    __syncthreads();
    if (warp == 0) {
        int v = wsum[lane];
        int wi = v;
        #pragma unroll
        for (int ofs = 1; ofs < 32; ofs <<= 1) {
            int t2 = __shfl_up_sync(0xffffffffu, wi, ofs);
            if (lane >= ofs) wi += t2;
        }
        woff[lane] = wi - v;
        if (lane == 31) total = wi;
    }
    __syncthreads();

    int run = woff[warp] + (incl - sum);
    for (int i = s0; i < s1; i++) {
        off[i] = run; pos[i] = run;
        run += cnt[i];
    }
    if (tid == 0) off[n] = total;
}

__global__ void build4_kernel(const int* __restrict__ s0, const int* __restrict__ d0, int* p0, int* e0,
                              const int* __restrict__ s1, const int* __restrict__ d1, int* p1, int* e1,
                              const int* __restrict__ s2, const int* __restrict__ d2, int* p2, int* e2,
                              const int* __restrict__ s3, const int* __restrict__ d3, int* p3, int* e3,
                              int E0, int E1, int E2, int E3) {
    int i = blockIdx.x * blockDim.x + threadIdx.x;
    if (i < E0) { int sl = atomicAdd(&p0[d0[i]], 1); e0[sl] = s0[i]; return; }
    i -= E0;
    if (i < E1) { int sl = atomicAdd(&p1[d1[i]], 1); e1[sl] = s1[i]; return; }
    i -= E1;
    if (i < E2) { int sl = atomicAdd(&p2[d2[i]], 1); e2[sl] = s2[i]; return; }
    i -= E2;
    if (i < E3) { int sl = atomicAdd(&p3[d3[i]], 1); e3[sl] = s3[i]; }
}

// ---------------- fp16 GEMM: C = lrelu(A @ W^T + b) (+ residual) ------------
// 128x128 tile, 256 thr, warp tile 32x64, wmma m16n16k16 fp16->fp32.
// cp.async 2-stage, K chunks of 32 halfs.
// smem stage: A[128][40]h (10240B) + B[128][40]h = 20480B; x2 = 40960B.
#define AT_BYTES 10240
#define STG_BYTES 20480
#define GEMM_SMEM 40960

template <bool RES>
__global__ __launch_bounds__(256, 2)
void gemm_lrelu_kernel(const __half* __restrict__ A, const __half* __restrict__ W,
                       const float* __restrict__ bias,
                       const float* __restrict__ resA, const float* __restrict__ resB,
                       int splitM, __half* __restrict__ C16, float* __restrict__ C32,
                       int M) {
    extern __shared__ __align__(16) char smem[];
    const int bm = blockIdx.x, bn = blockIdx.y;
    const int t = threadIdx.x;
    const int wid = t >> 5;
    const int wm = wid >> 1;      // 0..3
    const int wn = wid & 1;       // 0..1
    const uint32_t sb = smem_u32(smem);

    wmma::fragment<wmma::accumulator, 16, 16, 16, float> acc[2][4];
    #pragma unroll
    for (int i = 0; i < 2; i++)
        #pragma unroll
        for (int j = 0; j < 4; j++) wmma::fill_fragment(acc[i][j], 0.0f);

    // per-chunk loads: A,B each 128 rows x 32 halfs = 512 x 16B; 2 per thread each
    auto prefetch = [&](int stage, int kb) {
        uint32_t baseA = sb + stage * STG_BYTES;
        uint32_t baseB = baseA + AT_BYTES;
        #pragma unroll
        for (int i = 0; i < 2; i++) {
            int idx = t + i * 256;
            int row = idx >> 2, seg = idx & 3;
            int grow = bm * 128 + row;
            if (grow > M - 1) grow = M - 1;
            CP_ASYNC16(baseA + (uint32_t)(row * 40 + seg * 8) * 2,
                       A + (size_t)grow * DIM + kb * 32 + seg * 8);
            CP_ASYNC16(baseB + (uint32_t)(row * 40 + seg * 8) * 2,
                       W + (size_t)(bn * 128 + row) * DIM + kb * 32 + seg * 8);
        }
        CP_COMMIT();
    };

    prefetch(0, 0);

    for (int kb = 0; kb < 8; kb++) {
        const int s = kb & 1;
        if (kb < 7) { prefetch(s ^ 1, kb + 1); CP_WAIT1(); }
        else        { CP_WAIT0(); }
        __syncthreads();

        __half (*As)[40] = (__half(*)[40])(smem + s * STG_BYTES);
        __half (*Bs)[40] = (__half(*)[40])(smem + s * STG_BYTES + AT_BYTES);

        #pragma unroll
        for (int kk = 0; kk < 2; kk++) {
            wmma::fragment<wmma::matrix_a, 16, 16, 16, __half, wmma::row_major> a[2];
            wmma::fragment<wmma::matrix_b, 16, 16, 16, __half, wmma::col_major> b[4];
            #pragma unroll
            for (int i = 0; i < 2; i++)
                wmma::load_matrix_sync(a[i], &As[wm * 32 + i * 16][kk * 16], 40);
            #pragma unroll
            for (int j = 0; j < 4; j++)
                wmma::load_matrix_sync(b[j], &Bs[wn * 64 + j * 16][kk * 16], 40);
            #pragma unroll
            for (int i = 0; i < 2; i++)
                #pragma unroll
                for (int j = 0; j < 4; j++)
                    wmma::mma_sync(acc[i][j], a[i], b[j], acc[i][j]);
        }
        __syncthreads();
    }

    // Epilogue via reused smem (Cs [4][32][68] f32 = 34816B), two warp-waves.
    float (*Cs)[32][68] = (float(*)[32][68])smem;
    #pragma unroll
    for (int w = 0; w < 2; w++) {
        if ((wid >> 2) == w) {
            int slot = wid & 3;
            #pragma unroll
            for (int i = 0; i < 2; i++)
                #pragma unroll
                for (int j = 0; j < 4; j++)
                    wmma::store_matrix_sync(&Cs[slot][i * 16][j * 16], acc[i][j], 68,
                                            wmma::mem_row_major);
        }
        __syncthreads();
        #pragma unroll
        for (int i = 0; i < 8; i++) {
            int idx = t + i * 256;
            int slot = idx >> 9;
            int within = idx & 511;
            int row = within >> 4, c4 = within & 15;
            int grow = bm * 128 + (w * 2 + (slot >> 1)) * 32 + row;
            if (grow >= M) continue;
            int col = bn * 128 + (slot & 1) * 64 + c4 * 4;
            float4 v = *(float4*)&Cs[slot][row][c4 * 4];
            float4 bb = *(const float4*)&bias[col];
            v.x += bb.x; v.y += bb.y; v.z += bb.z; v.w += bb.w;
            v.x = v.x >= 0.f ? v.x : 0.01f * v.x;
            v.y = v.y >= 0.f ? v.y : 0.01f * v.y;
            v.z = v.z >= 0.f ? v.z : 0.01f * v.z;
            v.w = v.w >= 0.f ? v.w : 0.01f * v.w;
            size_t gi = (size_t)grow * DIM + col;
            if (RES) {
                const float* rp = (grow < splitM)
                    ? &resA[(size_t)grow * DIM + col]
                    : &resB[(size_t)(grow - splitM) * DIM + col];
                float4 f = *(const float4*)rp;
                v.x += f.x; v.y += f.y; v.z += f.z; v.w += f.w;
                *(float4*)&C32[gi] = v;
            } else {
                half2 h0 = __floats2half2_rn(v.x, v.y);
                half2 h1 = __floats2half2_rn(v.z, v.w);
                *(uint2*)&C16[gi] = make_uint2(*(uint32_t*)&h0, *(uint32_t*)&h1);
            }
        }
        __syncthreads();
    }
}

// ---------------- aggregation (fp16 in/out, fp32 accum) ----------------------
// 32 threads per dst row (8 halfs = 16B per thread), 8 rows per 256-block.
__global__ void agg2_kernel(const __half* __restrict__ WhA, const int* __restrict__ offA,
                            const int* __restrict__ eA,
                            const __half* __restrict__ WhB, const int* __restrict__ offB,
                            const int* __restrict__ eB,
                            __half* __restrict__ h, int n) {
    int d = blockIdx.x * 8 + (threadIdx.x >> 5);
    int c = threadIdx.x & 31;
    if (d >= n) return;

    const uint4* A4 = (const uint4*)WhA;   // 32 uint4 per row
    const uint4* B4 = (const uint4*)WhB;

    float acc[8];
    #pragma unroll
    for (int k = 0; k < 8; k++) acc[k] = 0.f;

    int s0 = offA[d], s1 = offA[d + 1];
    for (int j = s0; j < s1; j++) {
        int s = __ldg(&eA[j]);
        uint4 v = __ldg(&A4[(size_t)s * 32 + c]);
        half2* hv = (half2*)&v;
        #pragma unroll
        for (int k = 0; k < 4; k++) {
            float2 f = __half22float2(hv[k]);
            acc[2 * k] += f.x; acc[2 * k + 1] += f.y;
        }
    }
    float invA = 0.5f / (float)max(s1 - s0, 1);
    float r[8];
    #pragma unroll
    for (int k = 0; k < 8; k++) { r[k] = acc[k] * invA; acc[k] = 0.f; }

    s0 = offB[d]; s1 = offB[d + 1];
    for (int j = s0; j < s1; j++) {
        int s = __ldg(&eB[j]);
        uint4 v = __ldg(&B4[(size_t)s * 32 + c]);
        half2* hv = (half2*)&v;
        #pragma unroll
        for (int k = 0; k < 4; k++) {
            float2 f = __half22float2(hv[k]);
            acc[2 * k] += f.x; acc[2 * k + 1] += f.y;
        }
    }
    float invB = 0.5f / (float)max(s1 - s0, 1);
    #pragma unroll
    for (int k = 0; k < 8; k++) r[k] += acc[k] * invB;

    uint4 o;
    half2 p0 = __floats2half2_rn(r[0], r[1]);
    half2 p1 = __floats2half2_rn(r[2], r[3]);
    half2 p2 = __floats2half2_rn(r[4], r[5]);
    half2 p3 = __floats2half2_rn(r[6], r[7]);
    o.x = *(uint32_t*)&p0; o.y = *(uint32_t*)&p1;
    o.z = *(uint32_t*)&p2; o.w = *(uint32_t*)&p3;
    ((uint4*)h)[(size_t)d * 32 + c] = o;
}

// ---------------- launch -----------------------------------------------------
extern "C" void kernel_launch(void* const* d_in, const int* in_sizes, int n_in,
                              void* d_out, int out_size) {
    const float* feat_table = (const float*)d_in[0];
    const float* feat_col   = (const float*)d_in[1];
    const float* W_t2c = (const float*)d_in[2];  const float* b_t2c = (const float*)d_in[3];
    const float* W_c2t = (const float*)d_in[4];  const float* b_c2t = (const float*)d_in[5];
    const float* W_c2c = (const float*)d_in[6];  const float* b_c2c = (const float*)d_in[7];
    const float* W_t2t = (const float*)d_in[8];  const float* b_t2t = (const float*)d_in[9];
    const float* W_h   = (const float*)d_in[10]; const float* b_h   = (const float*)d_in[11];
    const int* src_t2c = (const int*)d_in[12]; const int* dst_t2c = (const int*)d_in[13];
    const int* src_c2t = (const int*)d_in[14]; const int* dst_c2t = (const int*)d_in[15];
    const int* src_c2c = (const int*)d_in[16]; const int* dst_c2c = (const int*)d_in[17];
    const int* src_t2t = (const int*)d_in[18]; const int* dst_t2t = (const int*)d_in[19];
    float* out = (float*)d_out;

    __half *feat16, *W16, *Wh_t2c, *Wh_c2t, *Wh_c2c, *Wh_t2t, *h16;
    int *cnt;
    int *off_t2c, *pos_t2c, *e_t2c;
    int *off_c2t, *pos_c2t, *e_c2t;
    int *off_c2c, *pos_c2c, *e_c2c;
    int *off_t2t, *pos_t2t, *e_t2t;
    cudaGetSymbolAddress((void**)&feat16, g_feat16);
    cudaGetSymbolAddress((void**)&W16, g_W16);
    cudaGetSymbolAddress((void**)&Wh_t2c, g_Wh_t2c);
    cudaGetSymbolAddress((void**)&Wh_c2t, g_Wh_c2t);
    cudaGetSymbolAddress((void**)&Wh_c2c, g_Wh_c2c);
    cudaGetSymbolAddress((void**)&Wh_t2t, g_Wh_t2t);
    cudaGetSymbolAddress((void**)&h16, g_h16);
    cudaGetSymbolAddress((void**)&cnt, g_cnt);
    cudaGetSymbolAddress((void**)&off_t2c, g_off_t2c); cudaGetSymbolAddress((void**)&pos_t2c, g_pos_t2c);
    cudaGetSymbolAddress((void**)&e_t2c, g_e_t2c);
    cudaGetSymbolAddress((void**)&off_c2t, g_off_c2t); cudaGetSymbolAddress((void**)&pos_c2t, g_pos_c2t);
    cudaGetSymbolAddress((void**)&e_c2t, g_e_c2t);
    cudaGetSymbolAddress((void**)&off_c2c, g_off_c2c); cudaGetSymbolAddress((void**)&pos_c2c, g_pos_c2c);
    cudaGetSymbolAddress((void**)&e_c2c, g_e_c2c);
    cudaGetSymbolAddress((void**)&off_t2t, g_off_t2t); cudaGetSymbolAddress((void**)&pos_t2t, g_pos_t2t);
    cudaGetSymbolAddress((void**)&e_t2t, g_e_t2t);

    cudaFuncSetAttribute(gemm_lrelu_kernel<false>, cudaFuncAttributeMaxDynamicSharedMemorySize, GEMM_SMEM);
    cudaFuncSetAttribute(gemm_lrelu_kernel<true>,  cudaFuncAttributeMaxDynamicSharedMemorySize, GEMM_SMEM);

    const int Et2c = in_sizes[12], Ec2t = in_sizes[14], Ec2c = in_sizes[16], Et2t = in_sizes[18];
    const int Eall = Et2c + Ec2t + Ec2c + Et2t;

    // conversions (overlap-friendly, independent of graph preprocessing)
    cvt_kernel<<<(NT * DIM / 4 + 255) / 256, 256>>>(feat_table, feat16, NT * DIM / 4);
    cvt_kernel<<<(NC * DIM / 4 + 255) / 256, 256>>>(feat_col, feat16 + (size_t)NT * DIM, NC * DIM / 4);
    cvt_w_kernel<<<(5 * 16384 + 255) / 256, 256>>>(W_t2c, W_c2t, W_c2c, W_t2t, W_h, W16);

    cudaMemsetAsync(cnt, 0, CNT_TOTAL * sizeof(int), 0);
    hist4_kernel<<<(Eall + 255) / 256, 256>>>(dst_t2c, dst_c2t, dst_c2c, dst_t2t,
                                              cnt, Et2c, Ec2t, Ec2c, Et2t);
    exscan4_kernel<<<4, 1024>>>(cnt, off_t2c, pos_t2c, off_c2t, pos_c2t,
                                off_c2c, pos_c2c, off_t2t, pos_t2t);
    build4_kernel<<<(Eall + 255) / 256, 256>>>(
        src_t2c, dst_t2c, pos_t2c, e_t2c,
        src_c2t, dst_c2t, pos_c2t, e_c2t,
        src_c2c, dst_c2c, pos_c2c, e_c2c,
        src_t2t, dst_t2t, pos_t2t, e_t2t,
        Et2c, Ec2t, Ec2c, Et2t);

    const __half* featT16 = feat16;
    const __half* featC16 = feat16 + (size_t)NT * DIM;
    const int gT = (NT + 127) / 128, gC = (NC + 127) / 128, gAll = (NT + NC + 127) / 128;

    gemm_lrelu_kernel<false><<<dim3(gT, 2), 256, GEMM_SMEM>>>(
        featT16, W16 + 0 * DIM * DIM, b_t2c, nullptr, nullptr, 0, Wh_t2c, nullptr, NT);
    gemm_lrelu_kernel<false><<<dim3(gC, 2), 256, GEMM_SMEM>>>(
        featC16, W16 + 1 * DIM * DIM, b_c2t, nullptr, nullptr, 0, Wh_c2t, nullptr, NC);
    gemm_lrelu_kernel<false><<<dim3(gC, 2), 256, GEMM_SMEM>>>(
        featC16, W16 + 2 * DIM * DIM, b_c2c, nullptr, nullptr, 0, Wh_c2c, nullptr, NC);
    gemm_lrelu_kernel<false><<<dim3(gT, 2), 256, GEMM_SMEM>>>(
        featT16, W16 + 3 * DIM * DIM, b_t2t, nullptr, nullptr, 0, Wh_t2t, nullptr, NT);

    agg2_kernel<<<(NT + 7) / 8, 256>>>(Wh_c2t, off_c2t, e_c2t, Wh_t2t, off_t2t, e_t2t, h16, NT);
    agg2_kernel<<<(NC + 7) / 8, 256>>>(Wh_t2c, off_t2c, e_t2c, Wh_c2c, off_c2c, e_c2c,
                                       h16 + (size_t)NT * DIM, NC);

    gemm_lrelu_kernel<true><<<dim3(gAll, 2), 256, GEMM_SMEM>>>(
        h16, W16 + 4 * DIM * DIM, b_h, feat_table, feat_col, NT, nullptr, out, NT + NC);
}

// round 6
// speedup vs baseline: 2.9337x; 1.0931x over previous
#include <cuda_runtime.h>
#include <cuda_fp16.h>
#include <mma.h>
#include <cstdint>

using namespace nvcuda;

#define NT 20000
#define NC 80000
#define DIM 256
#define E_T2C 320000
#define E_C2T 320000
#define E_C2C 640000
#define E_T2T 160000

// ---------------- scratch (device globals; no allocations allowed) ----------
__device__ __half g_feat16[(size_t)(NT + NC) * DIM];       // [table | column]
__device__ __half g_W16[5 * DIM * DIM];                    // t2c,c2t,c2c,t2t,h
__device__ __half g_Wh_t2c[(size_t)NT * DIM];
__device__ __half g_Wh_c2t[(size_t)NC * DIM];
__device__ __half g_Wh_c2c[(size_t)NC * DIM];
__device__ __half g_Wh_t2t[(size_t)NT * DIM];
__device__ __half g_h16[(size_t)(NT + NC) * DIM];

#define CNT_T2C 0
#define CNT_C2T NC
#define CNT_C2C (NC + NT)
#define CNT_T2T (NC + NT + NC)
#define CNT_TOTAL (2 * NC + 2 * NT)
__device__ int g_cnt[CNT_TOTAL];
__device__ int g_off_t2c[NC + 1]; __device__ int g_pos_t2c[NC]; __device__ int g_e_t2c[E_T2C];
__device__ int g_off_c2t[NT + 1]; __device__ int g_pos_c2t[NT]; __device__ int g_e_c2t[E_C2T];
__device__ int g_off_c2c[NC + 1]; __device__ int g_pos_c2c[NC]; __device__ int g_e_c2c[E_C2C];
__device__ int g_off_t2t[NT + 1]; __device__ int g_pos_t2t[NT]; __device__ int g_e_t2t[E_T2T];

// ---------------- helpers ----------------------------------------------------
__device__ __forceinline__ uint32_t smem_u32(const void* p) {
    uint32_t a;
    asm("{ .reg .u64 t; cvta.to.shared.u64 t, %1; cvt.u32.u64 %0, t; }" : "=r"(a) : "l"(p));
    return a;
}
#define CP_ASYNC16(dst, src) \
    asm volatile("cp.async.cg.shared.global [%0], [%1], 16;" :: "r"(dst), "l"(src))
#define CP_COMMIT() asm volatile("cp.async.commit_group;" ::: "memory")
#define CP_WAIT1() asm volatile("cp.async.wait_group 1;" ::: "memory")
#define CP_WAIT0() asm volatile("cp.async.wait_group 0;" ::: "memory")

// ---------------- conversion kernels -----------------------------------------
__global__ void cvt_feat_kernel(const float* __restrict__ ft, const float* __restrict__ fc,
                                __half* __restrict__ dst) {
    int i = blockIdx.x * blockDim.x + threadIdx.x;   // float4 index over NT+NC rows
    const int n4T = NT * DIM / 4;
    const int n4 = (NT + NC) * DIM / 4;
    if (i >= n4) return;
    float4 v = (i < n4T) ? ((const float4*)ft)[i] : ((const float4*)fc)[i - n4T];
    half2* d2 = (half2*)dst;
    d2[2 * i]     = __floats2half2_rn(v.x, v.y);
    d2[2 * i + 1] = __floats2half2_rn(v.z, v.w);
}

__global__ void cvt_w_kernel(const float* __restrict__ w0, const float* __restrict__ w1,
                             const float* __restrict__ w2, const float* __restrict__ w3,
                             const float* __restrict__ w4, __half* __restrict__ dst) {
    int i = blockIdx.x * blockDim.x + threadIdx.x;   // float4 index, 5*16384 total
    if (i >= 5 * 16384) return;
    const float* srcs[5] = {w0, w1, w2, w3, w4};
    const float* s = srcs[i >> 14];
    int j = i & 16383;
    float4 v = ((const float4*)s)[j];
    half2* d2 = (half2*)dst;
    d2[2 * i]     = __floats2half2_rn(v.x, v.y);
    d2[2 * i + 1] = __floats2half2_rn(v.z, v.w);
}

// ---------------- graph preprocessing ----------------------------------------
__global__ void hist4_kernel(const int* __restrict__ d0, const int* __restrict__ d1,
                             const int* __restrict__ d2, const int* __restrict__ d3,
                             int* __restrict__ cnt,
                             int E0, int E1, int E2, int E3) {
    int i = blockIdx.x * blockDim.x + threadIdx.x;
    if (i < E0) { atomicAdd(&cnt[CNT_T2C + d0[i]], 1); return; }
    i -= E0;
    if (i < E1) { atomicAdd(&cnt[CNT_C2T + d1[i]], 1); return; }
    i -= E1;
    if (i < E2) { atomicAdd(&cnt[CNT_C2C + d2[i]], 1); return; }
    i -= E2;
    if (i < E3) { atomicAdd(&cnt[CNT_T2T + d3[i]], 1); }
}

__global__ void exscan4_kernel(const int* __restrict__ cntbase,
                               int* o0, int* p0, int* o1, int* p1,
                               int* o2, int* p2, int* o3, int* p3) {
    const int* cnt; int* off; int* pos; int n;
    switch (blockIdx.x) {
        case 0: cnt = cntbase + CNT_T2C; off = o0; pos = p0; n = NC; break;
        case 1: cnt = cntbase + CNT_C2T; off = o1; pos = p1; n = NT; break;
        case 2: cnt = cntbase + CNT_C2C; off = o2; pos = p2; n = NC; break;
        default: cnt = cntbase + CNT_T2T; off = o3; pos = p3; n = NT; break;
    }
    const int tid = threadIdx.x;
    const int lane = tid & 31, warp = tid >> 5;
    const int seg = (n + 1023) / 1024;
    const int s0 = min(tid * seg, n), s1 = min(s0 + seg, n);

    int sum = 0;
    for (int i = s0; i < s1; i++) sum += cnt[i];

    int incl = sum;
    #pragma unroll
    for (int ofs = 1; ofs < 32; ofs <<= 1) {
        int v = __shfl_up_sync(0xffffffffu, incl, ofs);
        if (lane >= ofs) incl += v;
    }
    __shared__ int wsum[32];
    __shared__ int woff[32];
    __shared__ int total;
    if (lane == 31) wsum[warp] = incl;
    __syncthreads();
    if (warp == 0) {
        int v = wsum[lane];
        int wi = v;
        #pragma unroll
        for (int ofs = 1; ofs < 32; ofs <<= 1) {
            int t2 = __shfl_up_sync(0xffffffffu, wi, ofs);
            if (lane >= ofs) wi += t2;
        }
        woff[lane] = wi - v;
        if (lane == 31) total = wi;
    }
    __syncthreads();

    int run = woff[warp] + (incl - sum);
    for (int i = s0; i < s1; i++) {
        off[i] = run; pos[i] = run;
        run += cnt[i];
    }
    if (tid == 0) off[n] = total;
}

__global__ void build4_kernel(const int* __restrict__ s0, const int* __restrict__ d0, int* p0, int* e0,
                              const int* __restrict__ s1, const int* __restrict__ d1, int* p1, int* e1,
                              const int* __restrict__ s2, const int* __restrict__ d2, int* p2, int* e2,
                              const int* __restrict__ s3, const int* __restrict__ d3, int* p3, int* e3,
                              int E0, int E1, int E2, int E3) {
    int i = blockIdx.x * blockDim.x + threadIdx.x;
    if (i < E0) { int sl = atomicAdd(&p0[d0[i]], 1); e0[sl] = s0[i]; return; }
    i -= E0;
    if (i < E1) { int sl = atomicAdd(&p1[d1[i]], 1); e1[sl] = s1[i]; return; }
    i -= E1;
    if (i < E2) { int sl = atomicAdd(&p2[d2[i]], 1); e2[sl] = s2[i]; return; }
    i -= E2;
    if (i < E3) { int sl = atomicAdd(&p3[d3[i]], 1); e3[sl] = s3[i]; }
}

// ---------------- fp16 GEMM core (KC=64, 2-stage cp.async) -------------------
// Tile 128x128, 256 thr, warp tile 32x64. K = 256 in 4 chunks of 64 halfs.
// stage: A[128][72]h (18432B) + B[128][72]h = 36864B; x2 = 73728B dyn smem.
#define AT_BYTES 18432
#define STG_BYTES 36864
#define GEMM_SMEM 73728

struct GemmCore {
    wmma::fragment<wmma::accumulator, 16, 16, 16, float> acc[2][4];
};

__device__ __forceinline__ void gemm_mainloop(
    const __half* __restrict__ A, const __half* __restrict__ W,
    char* smem, uint32_t sb, int bm, int M, int t, int wm, int wn,
    GemmCore& g) {
    #pragma unroll
    for (int i = 0; i < 2; i++)
        #pragma unroll
        for (int j = 0; j < 4; j++) wmma::fill_fragment(g.acc[i][j], 0.0f);

    // per chunk: A,B each 128 rows x 64 halfs = 1024 x 16B; 4/thread each
    auto prefetch = [&](int stage, int kb) {
        uint32_t baseA = sb + stage * STG_BYTES;
        uint32_t baseB = baseA + AT_BYTES;
        #pragma unroll
        for (int i = 0; i < 4; i++) {
            int idx = t + i * 256;
            int row = idx >> 3, seg = idx & 7;
            int grow = bm * 128 + row;
            if (grow > M - 1) grow = M - 1;
            CP_ASYNC16(baseA + (uint32_t)(row * 72 + seg * 8) * 2,
                       A + (size_t)grow * DIM + kb * 64 + seg * 8);
            CP_ASYNC16(baseB + (uint32_t)(row * 72 + seg * 8) * 2,
                       W + (size_t)row * DIM + kb * 64 + seg * 8);
        }
        CP_COMMIT();
    };

    prefetch(0, 0);

    for (int kb = 0; kb < 4; kb++) {
        const int s = kb & 1;
        if (kb < 3) { prefetch(s ^ 1, kb + 1); CP_WAIT1(); }
        else        { CP_WAIT0(); }
        __syncthreads();

        __half (*As)[72] = (__half(*)[72])(smem + s * STG_BYTES);
        __half (*Bs)[72] = (__half(*)[72])(smem + s * STG_BYTES + AT_BYTES);

        #pragma unroll
        for (int kk = 0; kk < 4; kk++) {
            wmma::fragment<wmma::matrix_a, 16, 16, 16, __half, wmma::row_major> a[2];
            wmma::fragment<wmma::matrix_b, 16, 16, 16, __half, wmma::col_major> b[4];
            #pragma unroll
            for (int i = 0; i < 2; i++)
                wmma::load_matrix_sync(a[i], &As[wm * 32 + i * 16][kk * 16], 72);
            #pragma unroll
            for (int j = 0; j < 4; j++)
                wmma::load_matrix_sync(b[j], &Bs[wn * 64 + j * 16][kk * 16], 72);
            #pragma unroll
            for (int i = 0; i < 2; i++)
                #pragma unroll
                for (int j = 0; j < 4; j++)
                    wmma::mma_sync(g.acc[i][j], a[i], b[j], g.acc[i][j]);
        }
        __syncthreads();
    }
}

// dual-weight Wh GEMM: grid (mtiles, 4); y>>1 selects weight/out, y&1 = col half
__global__ __launch_bounds__(256, 2)
void gemm_dual_kernel(const __half* __restrict__ A,
                      const __half* __restrict__ W0, const __half* __restrict__ W1,
                      const float* __restrict__ bias0, const float* __restrict__ bias1,
                      __half* __restrict__ out0, __half* __restrict__ out1, int M) {
    extern __shared__ __align__(16) char smem[];
    const int bm = blockIdx.x, by = blockIdx.y;
    const int which = by >> 1, bn = by & 1;
    const __half* W = which ? W1 : W0;
    const float* bias = which ? bias1 : bias0;
    __half* out = which ? out1 : out0;

    const int t = threadIdx.x;
    const int wid = t >> 5;
    const int wm = wid >> 1, wn = wid & 1;
    const uint32_t sb = smem_u32(smem);

    GemmCore g;
    gemm_mainloop(A, W + (size_t)bn * 128 * DIM, smem, sb, bm, M, t, wm, wn, g);

    float (*Cs)[32][68] = (float(*)[32][68])smem;
    #pragma unroll
    for (int w = 0; w < 2; w++) {
        if ((wid >> 2) == w) {
            int slot = wid & 3;
            #pragma unroll
            for (int i = 0; i < 2; i++)
                #pragma unroll
                for (int j = 0; j < 4; j++)
                    wmma::store_matrix_sync(&Cs[slot][i * 16][j * 16], g.acc[i][j], 68,
                                            wmma::mem_row_major);
        }
        __syncthreads();
        #pragma unroll
        for (int i = 0; i < 8; i++) {
            int idx = t + i * 256;
            int slot = idx >> 9;
            int within = idx & 511;
            int row = within >> 4, c4 = within & 15;
            int grow = bm * 128 + (w * 2 + (slot >> 1)) * 32 + row;
            if (grow >= M) continue;
            int col = bn * 128 + (slot & 1) * 64 + c4 * 4;
            float4 v = *(float4*)&Cs[slot][row][c4 * 4];
            float4 bb = *(const float4*)&bias[col];
            v.x += bb.x; v.y += bb.y; v.z += bb.z; v.w += bb.w;
            v.x = v.x >= 0.f ? v.x : 0.01f * v.x;
            v.y = v.y >= 0.f ? v.y : 0.01f * v.y;
            v.z = v.z >= 0.f ? v.z : 0.01f * v.z;
            v.w = v.w >= 0.f ? v.w : 0.01f * v.w;
            half2 h0 = __floats2half2_rn(v.x, v.y);
            half2 h1 = __floats2half2_rn(v.z, v.w);
            *(uint2*)&out[(size_t)grow * DIM + col] =
                make_uint2(*(uint32_t*)&h0, *(uint32_t*)&h1);
        }
        __syncthreads();
    }
}

// final GEMM: +residual, fp32 out. grid (mtiles, 2)
__global__ __launch_bounds__(256, 2)
void gemm_final_kernel(const __half* __restrict__ A, const __half* __restrict__ W,
                       const float* __restrict__ bias,
                       const float* __restrict__ resA, const float* __restrict__ resB,
                       int splitM, float* __restrict__ C, int M) {
    extern __shared__ __align__(16) char smem[];
    const int bm = blockIdx.x, bn = blockIdx.y;
    const int t = threadIdx.x;
    const int wid = t >> 5;
    const int wm = wid >> 1, wn = wid & 1;
    const uint32_t sb = smem_u32(smem);

    GemmCore g;
    gemm_mainloop(A, W + (size_t)bn * 128 * DIM, smem, sb, bm, M, t, wm, wn, g);

    float (*Cs)[32][68] = (float(*)[32][68])smem;
    #pragma unroll
    for (int w = 0; w < 2; w++) {
        if ((wid >> 2) == w) {
            int slot = wid & 3;
            #pragma unroll
            for (int i = 0; i < 2; i++)
                #pragma unroll
                for (int j = 0; j < 4; j++)
                    wmma::store_matrix_sync(&Cs[slot][i * 16][j * 16], g.acc[i][j], 68,
                                            wmma::mem_row_major);
        }
        __syncthreads();
        #pragma unroll
        for (int i = 0; i < 8; i++) {
            int idx = t + i * 256;
            int slot = idx >> 9;
            int within = idx & 511;
            int row = within >> 4, c4 = within & 15;
            int grow = bm * 128 + (w * 2 + (slot >> 1)) * 32 + row;
            if (grow >= M) continue;
            int col = bn * 128 + (slot & 1) * 64 + c4 * 4;
            float4 v = *(float4*)&Cs[slot][row][c4 * 4];
            float4 bb = *(const float4*)&bias[col];
            v.x += bb.x; v.y += bb.y; v.z += bb.z; v.w += bb.w;
            v.x = v.x >= 0.f ? v.x : 0.01f * v.x;
            v.y = v.y >= 0.f ? v.y : 0.01f * v.y;
            v.z = v.z >= 0.f ? v.z : 0.01f * v.z;
            v.w = v.w >= 0.f ? v.w : 0.01f * v.w;
            const float* rp = (grow < splitM)
                ? &resA[(size_t)grow * DIM + col]
                : &resB[(size_t)(grow - splitM) * DIM + col];
            float4 f = *(const float4*)rp;
            v.x += f.x; v.y += f.y; v.z += f.z; v.w += f.w;
            *(float4*)&C[(size_t)grow * DIM + col] = v;
        }
        __syncthreads();
    }
}

// ---------------- aggregation (fp16 in/out, fp32 accum, 2x unrolled) ---------
__global__ void agg2_kernel(const __half* __restrict__ WhA, const int* __restrict__ offA,
                            const int* __restrict__ eA,
                            const __half* __restrict__ WhB, const int* __restrict__ offB,
                            const int* __restrict__ eB,
                            __half* __restrict__ h, int n) {
    int d = blockIdx.x * 8 + (threadIdx.x >> 5);
    int c = threadIdx.x & 31;
    if (d >= n) return;

    const uint4* A4 = (const uint4*)WhA;
    const uint4* B4 = (const uint4*)WhB;

    float acc[8];
    #pragma unroll
    for (int k = 0; k < 8; k++) acc[k] = 0.f;

    auto addv = [&](uint4 v) {
        half2* hv = (half2*)&v;
        #pragma unroll
        for (int k = 0; k < 4; k++) {
            float2 f = __half22float2(hv[k]);
            acc[2 * k] += f.x; acc[2 * k + 1] += f.y;
        }
    };

    int s0 = offA[d], s1 = offA[d + 1];
    int j = s0;
    for (; j + 1 < s1; j += 2) {
        int sa = __ldg(&eA[j]), sb2 = __ldg(&eA[j + 1]);
        uint4 va = __ldg(&A4[(size_t)sa * 32 + c]);
        uint4 vb = __ldg(&A4[(size_t)sb2 * 32 + c]);
        addv(va); addv(vb);
    }
    if (j < s1) addv(__ldg(&A4[(size_t)__ldg(&eA[j]) * 32 + c]));
    float invA = 0.5f / (float)max(s1 - s0, 1);
    float r[8];
    #pragma unroll
    for (int k = 0; k < 8; k++) { r[k] = acc[k] * invA; acc[k] = 0.f; }

    s0 = offB[d]; s1 = offB[d + 1];
    j = s0;
    for (; j + 1 < s1; j += 2) {
        int sa = __ldg(&eB[j]), sb2 = __ldg(&eB[j + 1]);
        uint4 va = __ldg(&B4[(size_t)sa * 32 + c]);
        uint4 vb = __ldg(&B4[(size_t)sb2 * 32 + c]);
        addv(va); addv(vb);
    }
    if (j < s1) addv(__ldg(&B4[(size_t)__ldg(&eB[j]) * 32 + c]));
    float invB = 0.5f / (float)max(s1 - s0, 1);
    #pragma unroll
    for (int k = 0; k < 8; k++) r[k] += acc[k] * invB;

    uint4 o;
    half2 p0 = __floats2half2_rn(r[0], r[1]);
    half2 p1 = __floats2half2_rn(r[2], r[3]);
    half2 p2 = __floats2half2_rn(r[4], r[5]);
    half2 p3 = __floats2half2_rn(r[6], r[7]);
    o.x = *(uint32_t*)&p0; o.y = *(uint32_t*)&p1;
    o.z = *(uint32_t*)&p2; o.w = *(uint32_t*)&p3;
    ((uint4*)h)[(size_t)d * 32 + c] = o;
}

// ---------------- launch -----------------------------------------------------
extern "C" void kernel_launch(void* const* d_in, const int* in_sizes, int n_in,
                              void* d_out, int out_size) {
    const float* feat_table = (const float*)d_in[0];
    const float* feat_col   = (const float*)d_in[1];
    const float* W_t2c = (const float*)d_in[2];  const float* b_t2c = (const float*)d_in[3];
    const float* W_c2t = (const float*)d_in[4];  const float* b_c2t = (const float*)d_in[5];
    const float* W_c2c = (const float*)d_in[6];  const float* b_c2c = (const float*)d_in[7];
    const float* W_t2t = (const float*)d_in[8];  const float* b_t2t = (const float*)d_in[9];
    const float* W_h   = (const float*)d_in[10]; const float* b_h   = (const float*)d_in[11];
    const int* src_t2c = (const int*)d_in[12]; const int* dst_t2c = (const int*)d_in[13];
    const int* src_c2t = (const int*)d_in[14]; const int* dst_c2t = (const int*)d_in[15];
    const int* src_c2c = (const int*)d_in[16]; const int* dst_c2c = (const int*)d_in[17];
    const int* src_t2t = (const int*)d_in[18]; const int* dst_t2t = (const int*)d_in[19];
    float* out = (float*)d_out;

    __half *feat16, *W16, *Wh_t2c, *Wh_c2t, *Wh_c2c, *Wh_t2t, *h16;
    int *cnt;
    int *off_t2c, *pos_t2c, *e_t2c;
    int *off_c2t, *pos_c2t, *e_c2t;
    int *off_c2c, *pos_c2c, *e_c2c;
    int *off_t2t, *pos_t2t, *e_t2t;
    cudaGetSymbolAddress((void**)&feat16, g_feat16);
    cudaGetSymbolAddress((void**)&W16, g_W16);
    cudaGetSymbolAddress((void**)&Wh_t2c, g_Wh_t2c);
    cudaGetSymbolAddress((void**)&Wh_c2t, g_Wh_c2t);
    cudaGetSymbolAddress((void**)&Wh_c2c, g_Wh_c2c);
    cudaGetSymbolAddress((void**)&Wh_t2t, g_Wh_t2t);
    cudaGetSymbolAddress((void**)&h16, g_h16);
    cudaGetSymbolAddress((void**)&cnt, g_cnt);
    cudaGetSymbolAddress((void**)&off_t2c, g_off_t2c); cudaGetSymbolAddress((void**)&pos_t2c, g_pos_t2c);
    cudaGetSymbolAddress((void**)&e_t2c, g_e_t2c);
    cudaGetSymbolAddress((void**)&off_c2t, g_off_c2t); cudaGetSymbolAddress((void**)&pos_c2t, g_pos_c2t);
    cudaGetSymbolAddress((void**)&e_c2t, g_e_c2t);
    cudaGetSymbolAddress((void**)&off_c2c, g_off_c2c); cudaGetSymbolAddress((void**)&pos_c2c, g_pos_c2c);
    cudaGetSymbolAddress((void**)&e_c2c, g_e_c2c);
    cudaGetSymbolAddress((void**)&off_t2t, g_off_t2t); cudaGetSymbolAddress((void**)&pos_t2t, g_pos_t2t);
    cudaGetSymbolAddress((void**)&e_t2t, g_e_t2t);

    cudaFuncSetAttribute(gemm_dual_kernel,  cudaFuncAttributeMaxDynamicSharedMemorySize, GEMM_SMEM);
    cudaFuncSetAttribute(gemm_final_kernel, cudaFuncAttributeMaxDynamicSharedMemorySize, GEMM_SMEM);

    const int Et2c = in_sizes[12], Ec2t = in_sizes[14], Ec2c = in_sizes[16], Et2t = in_sizes[18];
    const int Eall = Et2c + Ec2t + Ec2c + Et2t;

    cvt_feat_kernel<<<((NT + NC) * DIM / 4 + 255) / 256, 256>>>(feat_table, feat_col, feat16);
    cvt_w_kernel<<<(5 * 16384 + 255) / 256, 256>>>(W_t2c, W_c2t, W_c2c, W_t2t, W_h, W16);

    cudaMemsetAsync(cnt, 0, CNT_TOTAL * sizeof(int), 0);
    hist4_kernel<<<(Eall + 255) / 256, 256>>>(dst_t2c, dst_c2t, dst_c2c, dst_t2t,
                                              cnt, Et2c, Ec2t, Ec2c, Et2t);
    exscan4_kernel<<<4, 1024>>>(cnt, off_t2c, pos_t2c, off_c2t, pos_c2t,
                                off_c2c, pos_c2c, off_t2t, pos_t2t);
    build4_kernel<<<(Eall + 255) / 256, 256>>>(
        src_t2c, dst_t2c, pos_t2c, e_t2c,
        src_c2t, dst_c2t, pos_c2t, e_c2t,
        src_c2c, dst_c2c, pos_c2c, e_c2c,
        src_t2t, dst_t2t, pos_t2t, e_t2t,
        Et2c, Ec2t, Ec2c, Et2t);

    const __half* featT16 = feat16;
    const __half* featC16 = feat16 + (size_t)NT * DIM;
    const int gT = (NT + 127) / 128, gC = (NC + 127) / 128, gAll = (NT + NC + 127) / 128;

    // table-sourced pair (t2c, t2t) and column-sourced pair (c2t, c2c)
    gemm_dual_kernel<<<dim3(gT, 4), 256, GEMM_SMEM>>>(
        featT16, W16 + 0 * DIM * DIM, W16 + 3 * DIM * DIM, b_t2c, b_t2t,
        Wh_t2c, Wh_t2t, NT);
    gemm_dual_kernel<<<dim3(gC, 4), 256, GEMM_SMEM>>>(
        featC16, W16 + 1 * DIM * DIM, W16 + 2 * DIM * DIM, b_c2t, b_c2c,
        Wh_c2t, Wh_c2c, NC);

    agg2_kernel<<<(NT + 7) / 8, 256>>>(Wh_c2t, off_c2t, e_c2t, Wh_t2t, off_t2t, e_t2t, h16, NT);
    agg2_kernel<<<(NC + 7) / 8, 256>>>(Wh_t2c, off_t2c, e_t2c, Wh_c2c, off_c2c, e_c2c,
                                       h16 + (size_t)NT * DIM, NC);

    gemm_final_kernel<<<dim3(gAll, 2), 256, GEMM_SMEM>>>(
        h16, W16 + 4 * DIM * DIM, b_h, feat_table, feat_col, NT, out, NT + NC);
}

// round 7
// speedup vs baseline: 3.2978x; 1.1241x over previous
#include <cuda_runtime.h>
#include <cuda_fp16.h>
#include <mma.h>
#include <cstdint>

using namespace nvcuda;

#define NT 20000
#define NC 80000
#define DIM 256
#define E_T2C 320000
#define E_C2T 320000
#define E_C2C 640000
#define E_T2T 160000

// ---------------- scratch (device globals; no allocations allowed) ----------
__device__ __half g_feat16[(size_t)(NT + NC) * DIM];       // [table | column]
__device__ __half g_W16[5 * DIM * DIM];                    // t2c,c2t,c2c,t2t,h
__device__ __half g_Wh_t2c[(size_t)NT * DIM];
__device__ __half g_Wh_c2t[(size_t)NC * DIM];
__device__ __half g_Wh_c2c[(size_t)NC * DIM];
__device__ __half g_Wh_t2t[(size_t)NT * DIM];
__device__ __half g_h16[(size_t)(NT + NC) * DIM];

#define CNT_T2C 0
#define CNT_C2T NC
#define CNT_C2C (NC + NT)
#define CNT_T2T (NC + NT + NC)
#define CNT_TOTAL (2 * NC + 2 * NT)
__device__ int g_cnt[CNT_TOTAL];
__device__ int g_off_t2c[NC + 1]; __device__ int g_pos_t2c[NC]; __device__ int g_e_t2c[E_T2C];
__device__ int g_off_c2t[NT + 1]; __device__ int g_pos_c2t[NT]; __device__ int g_e_c2t[E_C2T];
__device__ int g_off_c2c[NC + 1]; __device__ int g_pos_c2c[NC]; __device__ int g_e_c2c[E_C2C];
__device__ int g_off_t2t[NT + 1]; __device__ int g_pos_t2t[NT]; __device__ int g_e_t2t[E_T2T];

// ---------------- helpers ----------------------------------------------------
__device__ __forceinline__ uint32_t smem_u32(const void* p) {
    uint32_t a;
    asm("{ .reg .u64 t; cvta.to.shared.u64 t, %1; cvt.u32.u64 %0, t; }" : "=r"(a) : "l"(p));
    return a;
}
#define CP_ASYNC16(dst, src) \
    asm volatile("cp.async.cg.shared.global [%0], [%1], 16;" :: "r"(dst), "l"(src))
#define CP_COMMIT() asm volatile("cp.async.commit_group;" ::: "memory")
#define CP_WAIT1() asm volatile("cp.async.wait_group 1;" ::: "memory")
#define CP_WAIT0() asm volatile("cp.async.wait_group 0;" ::: "memory")

__device__ __forceinline__ int warp_iscan(int v, int lane) {
    #pragma unroll
    for (int ofs = 1; ofs < 32; ofs <<= 1) {
        int t = __shfl_up_sync(0xffffffffu, v, ofs);
        if (lane >= ofs) v += t;
    }
    return v;
}

// ---------------- conversion kernels -----------------------------------------
__global__ void cvt_feat_kernel(const float* __restrict__ ft, const float* __restrict__ fc,
                                __half* __restrict__ dst) {
    int i = blockIdx.x * blockDim.x + threadIdx.x;
    const int n4T = NT * DIM / 4;
    const int n4 = (NT + NC) * DIM / 4;
    if (i >= n4) return;
    float4 v = (i < n4T) ? ((const float4*)ft)[i] : ((const float4*)fc)[i - n4T];
    half2* d2 = (half2*)dst;
    d2[2 * i]     = __floats2half2_rn(v.x, v.y);
    d2[2 * i + 1] = __floats2half2_rn(v.z, v.w);
}

__global__ void cvt_w_kernel(const float* __restrict__ w0, const float* __restrict__ w1,
                             const float* __restrict__ w2, const float* __restrict__ w3,
                             const float* __restrict__ w4, __half* __restrict__ dst) {
    int i = blockIdx.x * blockDim.x + threadIdx.x;
    if (i >= 5 * 16384) return;
    const float* srcs[5] = {w0, w1, w2, w3, w4};
    const float* s = srcs[i >> 14];
    int j = i & 16383;
    float4 v = ((const float4*)s)[j];
    half2* d2 = (half2*)dst;
    d2[2 * i]     = __floats2half2_rn(v.x, v.y);
    d2[2 * i + 1] = __floats2half2_rn(v.z, v.w);
}

// ---------------- graph preprocessing ----------------------------------------
__global__ void hist4_kernel(const int* __restrict__ d0, const int* __restrict__ d1,
                             const int* __restrict__ d2, const int* __restrict__ d3,
                             int* __restrict__ cnt,
                             int E0, int E1, int E2, int E3) {
    int i = blockIdx.x * blockDim.x + threadIdx.x;
    if (i < E0) { atomicAdd(&cnt[CNT_T2C + d0[i]], 1); return; }
    i -= E0;
    if (i < E1) { atomicAdd(&cnt[CNT_C2T + d1[i]], 1); return; }
    i -= E1;
    if (i < E2) { atomicAdd(&cnt[CNT_C2C + d2[i]], 1); return; }
    i -= E2;
    if (i < E3) { atomicAdd(&cnt[CNT_T2T + d3[i]], 1); }
}

// chunk-wise COALESCED exclusive scan; 4 blocks, one per etype.
__global__ void exscan4_kernel(const int* __restrict__ cntbase,
                               int* o0, int* p0, int* o1, int* p1,
                               int* o2, int* p2, int* o3, int* p3) {
    const int* cnt; int* off; int* pos; int n;
    switch (blockIdx.x) {
        case 0: cnt = cntbase + CNT_T2C; off = o0; pos = p0; n = NC; break;
        case 1: cnt = cntbase + CNT_C2T; off = o1; pos = p1; n = NT; break;
        case 2: cnt = cntbase + CNT_C2C; off = o2; pos = p2; n = NC; break;
        default: cnt = cntbase + CNT_T2T; off = o3; pos = p3; n = NT; break;
    }
    const int tid = threadIdx.x;            // 1024 threads
    const int lane = tid & 31, warp = tid >> 5;
    __shared__ int wpart[32];
    __shared__ int chunk_total;
    int carry = 0;

    for (int base = 0; base < n; base += 1024) {
        int i = base + tid;
        int v = (i < n) ? cnt[i] : 0;        // coalesced
        int incl = warp_iscan(v, lane);
        if (lane == 31) wpart[warp] = incl;
        __syncthreads();
        if (warp == 0) {
            int wv = wpart[lane];
            int ws = warp_iscan(wv, lane);
            wpart[lane] = ws - wv;           // exclusive warp offset
            if (lane == 31) chunk_total = ws;
        }
        __syncthreads();
        int excl = carry + wpart[warp] + incl - v;
        if (i < n) { off[i] = excl; pos[i] = excl; }   // coalesced
        carry += chunk_total;
        __syncthreads();                      // protect wpart/chunk_total reuse
    }
    if (tid == 0) off[n] = carry;
}

__global__ void build4_kernel(const int* __restrict__ s0, const int* __restrict__ d0, int* p0, int* e0,
                              const int* __restrict__ s1, const int* __restrict__ d1, int* p1, int* e1,
                              const int* __restrict__ s2, const int* __restrict__ d2, int* p2, int* e2,
                              const int* __restrict__ s3, const int* __restrict__ d3, int* p3, int* e3,
                              int E0, int E1, int E2, int E3) {
    int i = blockIdx.x * blockDim.x + threadIdx.x;
    if (i < E0) { int sl = atomicAdd(&p0[d0[i]], 1); e0[sl] = s0[i]; return; }
    i -= E0;
    if (i < E1) { int sl = atomicAdd(&p1[d1[i]], 1); e1[sl] = s1[i]; return; }
    i -= E1;
    if (i < E2) { int sl = atomicAdd(&p2[d2[i]], 1); e2[sl] = s2[i]; return; }
    i -= E2;
    if (i < E3) { int sl = atomicAdd(&p3[d3[i]], 1); e3[sl] = s3[i]; }
}

// ---------------- fp16 GEMM core (KC=64, 2-stage cp.async) -------------------
#define AT_BYTES 18432
#define STG_BYTES 36864
#define GEMM_SMEM 73728

struct GemmCore {
    wmma::fragment<wmma::accumulator, 16, 16, 16, float> acc[2][4];
};

__device__ __forceinline__ void gemm_mainloop(
    const __half* __restrict__ A, const __half* __restrict__ W,
    char* smem, uint32_t sb, int bm, int M, int t, int wm, int wn,
    GemmCore& g) {
    #pragma unroll
    for (int i = 0; i < 2; i++)
        #pragma unroll
        for (int j = 0; j < 4; j++) wmma::fill_fragment(g.acc[i][j], 0.0f);

    auto prefetch = [&](int stage, int kb) {
        uint32_t baseA = sb + stage * STG_BYTES;
        uint32_t baseB = baseA + AT_BYTES;
        #pragma unroll
        for (int i = 0; i < 4; i++) {
            int idx = t + i * 256;
            int row = idx >> 3, seg = idx & 7;
            int grow = bm * 128 + row;
            if (grow > M - 1) grow = M - 1;
            CP_ASYNC16(baseA + (uint32_t)(row * 72 + seg * 8) * 2,
                       A + (size_t)grow * DIM + kb * 64 + seg * 8);
            CP_ASYNC16(baseB + (uint32_t)(row * 72 + seg * 8) * 2,
                       W + (size_t)row * DIM + kb * 64 + seg * 8);
        }
        CP_COMMIT();
    };

    prefetch(0, 0);

    for (int kb = 0; kb < 4; kb++) {
        const int s = kb & 1;
        if (kb < 3) { prefetch(s ^ 1, kb + 1); CP_WAIT1(); }
        else        { CP_WAIT0(); }
        __syncthreads();

        __half (*As)[72] = (__half(*)[72])(smem + s * STG_BYTES);
        __half (*Bs)[72] = (__half(*)[72])(smem + s * STG_BYTES + AT_BYTES);

        #pragma unroll
        for (int kk = 0; kk < 4; kk++) {
            wmma::fragment<wmma::matrix_a, 16, 16, 16, __half, wmma::row_major> a[2];
            wmma::fragment<wmma::matrix_b, 16, 16, 16, __half, wmma::col_major> b[4];
            #pragma unroll
            for (int i = 0; i < 2; i++)
                wmma::load_matrix_sync(a[i], &As[wm * 32 + i * 16][kk * 16], 72);
            #pragma unroll
            for (int j = 0; j < 4; j++)
                wmma::load_matrix_sync(b[j], &Bs[wn * 64 + j * 16][kk * 16], 72);
            #pragma unroll
            for (int i = 0; i < 2; i++)
                #pragma unroll
                for (int j = 0; j < 4; j++)
                    wmma::mma_sync(g.acc[i][j], a[i], b[j], g.acc[i][j]);
        }
        __syncthreads();
    }
}

// dual-weight Wh GEMM: grid (mtiles, 4); y>>1 selects weight/out, y&1 = col half
__global__ __launch_bounds__(256, 2)
void gemm_dual_kernel(const __half* __restrict__ A,
                      const __half* __restrict__ W0, const __half* __restrict__ W1,
                      const float* __restrict__ bias0, const float* __restrict__ bias1,
                      __half* __restrict__ out0, __half* __restrict__ out1, int M) {
    extern __shared__ __align__(16) char smem[];
    const int bm = blockIdx.x, by = blockIdx.y;
    const int which = by >> 1, bn = by & 1;
    const __half* W = which ? W1 : W0;
    const float* bias = which ? bias1 : bias0;
    __half* out = which ? out1 : out0;

    const int t = threadIdx.x;
    const int wid = t >> 5;
    const int wm = wid >> 1, wn = wid & 1;
    const uint32_t sb = smem_u32(smem);

    GemmCore g;
    gemm_mainloop(A, W + (size_t)bn * 128 * DIM, smem, sb, bm, M, t, wm, wn, g);

    float (*Cs)[32][68] = (float(*)[32][68])smem;
    #pragma unroll
    for (int w = 0; w < 2; w++) {
        if ((wid >> 2) == w) {
            int slot = wid & 3;
            #pragma unroll
            for (int i = 0; i < 2; i++)
                #pragma unroll
                for (int j = 0; j < 4; j++)
                    wmma::store_matrix_sync(&Cs[slot][i * 16][j * 16], g.acc[i][j], 68,
                                            wmma::mem_row_major);
        }
        __syncthreads();
        #pragma unroll
        for (int i = 0; i < 8; i++) {
            int idx = t + i * 256;
            int slot = idx >> 9;
            int within = idx & 511;
            int row = within >> 4, c4 = within & 15;
            int grow = bm * 128 + (w * 2 + (slot >> 1)) * 32 + row;
            if (grow >= M) continue;
            int col = bn * 128 + (slot & 1) * 64 + c4 * 4;
            float4 v = *(float4*)&Cs[slot][row][c4 * 4];
            float4 bb = *(const float4*)&bias[col];
            v.x += bb.x; v.y += bb.y; v.z += bb.z; v.w += bb.w;
            v.x = v.x >= 0.f ? v.x : 0.01f * v.x;
            v.y = v.y >= 0.f ? v.y : 0.01f * v.y;
            v.z = v.z >= 0.f ? v.z : 0.01f * v.z;
            v.w = v.w >= 0.f ? v.w : 0.01f * v.w;
            half2 h0 = __floats2half2_rn(v.x, v.y);
            half2 h1 = __floats2half2_rn(v.z, v.w);
            *(uint2*)&out[(size_t)grow * DIM + col] =
                make_uint2(*(uint32_t*)&h0, *(uint32_t*)&h1);
        }
        __syncthreads();
    }
}

// final GEMM: +residual, fp32 out. grid (mtiles, 2)
__global__ __launch_bounds__(256, 2)
void gemm_final_kernel(const __half* __restrict__ A, const __half* __restrict__ W,
                       const float* __restrict__ bias,
                       const float* __restrict__ resA, const float* __restrict__ resB,
                       int splitM, float* __restrict__ C, int M) {
    extern __shared__ __align__(16) char smem[];
    const int bm = blockIdx.x, bn = blockIdx.y;
    const int t = threadIdx.x;
    const int wid = t >> 5;
    const int wm = wid >> 1, wn = wid & 1;
    const uint32_t sb = smem_u32(smem);

    GemmCore g;
    gemm_mainloop(A, W + (size_t)bn * 128 * DIM, smem, sb, bm, M, t, wm, wn, g);

    float (*Cs)[32][68] = (float(*)[32][68])smem;
    #pragma unroll
    for (int w = 0; w < 2; w++) {
        if ((wid >> 2) == w) {
            int slot = wid & 3;
            #pragma unroll
            for (int i = 0; i < 2; i++)
                #pragma unroll
                for (int j = 0; j < 4; j++)
                    wmma::store_matrix_sync(&Cs[slot][i * 16][j * 16], g.acc[i][j], 68,
                                            wmma::mem_row_major);
        }
        __syncthreads();
        #pragma unroll
        for (int i = 0; i < 8; i++) {
            int idx = t + i * 256;
            int slot = idx >> 9;
            int within = idx & 511;
            int row = within >> 4, c4 = within & 15;
            int grow = bm * 128 + (w * 2 + (slot >> 1)) * 32 + row;
            if (grow >= M) continue;
            int col = bn * 128 + (slot & 1) * 64 + c4 * 4;
            float4 v = *(float4*)&Cs[slot][row][c4 * 4];
            float4 bb = *(const float4*)&bias[col];
            v.x += bb.x; v.y += bb.y; v.z += bb.z; v.w += bb.w;
            v.x = v.x >= 0.f ? v.x : 0.01f * v.x;
            v.y = v.y >= 0.f ? v.y : 0.01f * v.y;
            v.z = v.z >= 0.f ? v.z : 0.01f * v.z;
            v.w = v.w >= 0.f ? v.w : 0.01f * v.w;
            const float* rp = (grow < splitM)
                ? &resA[(size_t)grow * DIM + col]
                : &resB[(size_t)(grow - splitM) * DIM + col];
            float4 f = *(const float4*)rp;
            v.x += f.x; v.y += f.y; v.z += f.z; v.w += f.w;
            *(float4*)&C[(size_t)grow * DIM + col] = v;
        }
        __syncthreads();
    }
}

// ---------------- aggregation (fp16 in/out, fp32 accum, 4x MLP) --------------
__global__ void agg2_kernel(const __half* __restrict__ WhA, const int* __restrict__ offA,
                            const int* __restrict__ eA,
                            const __half* __restrict__ WhB, const int* __restrict__ offB,
                            const int* __restrict__ eB,
                            __half* __restrict__ h, int n) {
    int d = blockIdx.x * 8 + (threadIdx.x >> 5);
    int c = threadIdx.x & 31;
    if (d >= n) return;

    const uint4* A4 = (const uint4*)WhA;
    const uint4* B4 = (const uint4*)WhB;

    float acc[8];
    #pragma unroll
    for (int k = 0; k < 8; k++) acc[k] = 0.f;

    auto addv = [&](uint4 v) {
        half2* hv = (half2*)&v;
        #pragma unroll
        for (int k = 0; k < 4; k++) {
            float2 f = __half22float2(hv[k]);
            acc[2 * k] += f.x; acc[2 * k + 1] += f.y;
        }
    };

    auto run = [&](const uint4* T4, const int* e, int s0, int s1) {
        int j = s0;
        for (; j + 3 < s1; j += 4) {
            int i0 = __ldg(&e[j]),     i1 = __ldg(&e[j + 1]);
            int i2 = __ldg(&e[j + 2]), i3 = __ldg(&e[j + 3]);
            uint4 v0 = __ldg(&T4[(size_t)i0 * 32 + c]);
            uint4 v1 = __ldg(&T4[(size_t)i1 * 32 + c]);
            uint4 v2 = __ldg(&T4[(size_t)i2 * 32 + c]);
            uint4 v3 = __ldg(&T4[(size_t)i3 * 32 + c]);
            addv(v0); addv(v1); addv(v2); addv(v3);
        }
        for (; j < s1; j++) addv(__ldg(&T4[(size_t)__ldg(&e[j]) * 32 + c]));
    };

    int s0 = offA[d], s1 = offA[d + 1];
    run(A4, eA, s0, s1);
    float invA = 0.5f / (float)max(s1 - s0, 1);
    float r[8];
    #pragma unroll
    for (int k = 0; k < 8; k++) { r[k] = acc[k] * invA; acc[k] = 0.f; }

    s0 = offB[d]; s1 = offB[d + 1];
    run(B4, eB, s0, s1);
    float invB = 0.5f / (float)max(s1 - s0, 1);
    #pragma unroll
    for (int k = 0; k < 8; k++) r[k] += acc[k] * invB;

    uint4 o;
    half2 p0 = __floats2half2_rn(r[0], r[1]);
    half2 p1 = __floats2half2_rn(r[2], r[3]);
    half2 p2 = __floats2half2_rn(r[4], r[5]);
    half2 p3 = __floats2half2_rn(r[6], r[7]);
    o.x = *(uint32_t*)&p0; o.y = *(uint32_t*)&p1;
    o.z = *(uint32_t*)&p2; o.w = *(uint32_t*)&p3;
    ((uint4*)h)[(size_t)d * 32 + c] = o;
}

// ---------------- launch -----------------------------------------------------
extern "C" void kernel_launch(void* const* d_in, const int* in_sizes, int n_in,
                              void* d_out, int out_size) {
    const float* feat_table = (const float*)d_in[0];
    const float* feat_col   = (const float*)d_in[1];
    const float* W_t2c = (const float*)d_in[2];  const float* b_t2c = (const float*)d_in[3];
    const float* W_c2t = (const float*)d_in[4];  const float* b_c2t = (const float*)d_in[5];
    const float* W_c2c = (const float*)d_in[6];  const float* b_c2c = (const float*)d_in[7];
    const float* W_t2t = (const float*)d_in[8];  const float* b_t2t = (const float*)d_in[9];
    const float* W_h   = (const float*)d_in[10]; const float* b_h   = (const float*)d_in[11];
    const int* src_t2c = (const int*)d_in[12]; const int* dst_t2c = (const int*)d_in[13];
    const int* src_c2t = (const int*)d_in[14]; const int* dst_c2t = (const int*)d_in[15];
    const int* src_c2c = (const int*)d_in[16]; const int* dst_c2c = (const int*)d_in[17];
    const int* src_t2t = (const int*)d_in[18]; const int* dst_t2t = (const int*)d_in[19];
    float* out = (float*)d_out;

    __half *feat16, *W16, *Wh_t2c, *Wh_c2t, *Wh_c2c, *Wh_t2t, *h16;
    int *cnt;
    int *off_t2c, *pos_t2c, *e_t2c;
    int *off_c2t, *pos_c2t, *e_c2t;
    int *off_c2c, *pos_c2c, *e_c2c;
    int *off_t2t, *pos_t2t, *e_t2t;
    cudaGetSymbolAddress((void**)&feat16, g_feat16);
    cudaGetSymbolAddress((void**)&W16, g_W16);
    cudaGetSymbolAddress((void**)&Wh_t2c, g_Wh_t2c);
    cudaGetSymbolAddress((void**)&Wh_c2t, g_Wh_c2t);
    cudaGetSymbolAddress((void**)&Wh_c2c, g_Wh_c2c);
    cudaGetSymbolAddress((void**)&Wh_t2t, g_Wh_t2t);
    cudaGetSymbolAddress((void**)&h16, g_h16);
    cudaGetSymbolAddress((void**)&cnt, g_cnt);
    cudaGetSymbolAddress((void**)&off_t2c, g_off_t2c); cudaGetSymbolAddress((void**)&pos_t2c, g_pos_t2c);
    cudaGetSymbolAddress((void**)&e_t2c, g_e_t2c);
    cudaGetSymbolAddress((void**)&off_c2t, g_off_c2t); cudaGetSymbolAddress((void**)&pos_c2t, g_pos_c2t);
    cudaGetSymbolAddress((void**)&e_c2t, g_e_c2t);
    cudaGetSymbolAddress((void**)&off_c2c, g_off_c2c); cudaGetSymbolAddress((void**)&pos_c2c, g_pos_c2c);
    cudaGetSymbolAddress((void**)&e_c2c, g_e_c2c);
    cudaGetSymbolAddress((void**)&off_t2t, g_off_t2t); cudaGetSymbolAddress((void**)&pos_t2t, g_pos_t2t);
    cudaGetSymbolAddress((void**)&e_t2t, g_e_t2t);

    cudaFuncSetAttribute(gemm_dual_kernel,  cudaFuncAttributeMaxDynamicSharedMemorySize, GEMM_SMEM);
    cudaFuncSetAttribute(gemm_final_kernel, cudaFuncAttributeMaxDynamicSharedMemorySize, GEMM_SMEM);

    const int Et2c = in_sizes[12], Ec2t = in_sizes[14], Ec2c = in_sizes[16], Et2t = in_sizes[18];
    const int Eall = Et2c + Ec2t + Ec2c + Et2t;

    cvt_feat_kernel<<<((NT + NC) * DIM / 4 + 255) / 256, 256>>>(feat_table, feat_col, feat16);
    cvt_w_kernel<<<(5 * 16384 + 255) / 256, 256>>>(W_t2c, W_c2t, W_c2c, W_t2t, W_h, W16);

    cudaMemsetAsync(cnt, 0, CNT_TOTAL * sizeof(int), 0);
    hist4_kernel<<<(Eall + 255) / 256, 256>>>(dst_t2c, dst_c2t, dst_c2c, dst_t2t,
                                              cnt, Et2c, Ec2t, Ec2c, Et2t);
    exscan4_kernel<<<4, 1024>>>(cnt, off_t2c, pos_t2c, off_c2t, pos_c2t,
                                off_c2c, pos_c2c, off_t2t, pos_t2t);
    build4_kernel<<<(Eall + 255) / 256, 256>>>(
        src_t2c, dst_t2c, pos_t2c, e_t2c,
        src_c2t, dst_c2t, pos_c2t, e_c2t,
        src_c2c, dst_c2c, pos_c2c, e_c2c,
        src_t2t, dst_t2t, pos_t2t, e_t2t,
        Et2c, Ec2t, Ec2c, Et2t);

    const __half* featT16 = feat16;
    const __half* featC16 = feat16 + (size_t)NT * DIM;
    const int gT = (NT + 127) / 128, gC = (NC + 127) / 128, gAll = (NT + NC + 127) / 128;

    gemm_dual_kernel<<<dim3(gT, 4), 256, GEMM_SMEM>>>(
        featT16, W16 + 0 * DIM * DIM, W16 + 3 * DIM * DIM, b_t2c, b_t2t,
        Wh_t2c, Wh_t2t, NT);
    gemm_dual_kernel<<<dim3(gC, 4), 256, GEMM_SMEM>>>(
        featC16, W16 + 1 * DIM * DIM, W16 + 2 * DIM * DIM, b_c2t, b_c2c,
        Wh_c2t, Wh_c2c, NC);

    agg2_kernel<<<(NT + 7) / 8, 256>>>(Wh_c2t, off_c2t, e_c2t, Wh_t2t, off_t2t, e_t2t, h16, NT);
    agg2_kernel<<<(NC + 7) / 8, 256>>>(Wh_t2c, off_t2c, e_t2c, Wh_c2c, off_c2c, e_c2c,
                                       h16 + (size_t)NT * DIM, NC);

    gemm_final_kernel<<<dim3(gAll, 2), 256, GEMM_SMEM>>>(
        h16, W16 + 4 * DIM * DIM, b_h, feat_table, feat_col, NT, out, NT + NC);
}

// round 8
// speedup vs baseline: 3.6825x; 1.1166x over previous
#include <cuda_runtime.h>
#include <cuda_fp16.h>
#include <mma.h>
#include <cstdint>

using namespace nvcuda;

#define NT 20000
#define NC 80000
#define DIM 256
#define E_T2C 320000
#define E_C2T 320000
#define E_C2C 640000
#define E_T2T 160000

// ---------------- scratch (device globals; no allocations allowed) ----------
__device__ __half g_feat16[(size_t)(NT + NC) * DIM];       // [table | column]
__device__ __half g_W16[5 * DIM * DIM];                    // t2c,c2t,c2c,t2t,h
__device__ __half g_Wh_t2c[(size_t)NT * DIM];
__device__ __half g_Wh_c2t[(size_t)NC * DIM];
__device__ __half g_Wh_c2c[(size_t)NC * DIM];
__device__ __half g_Wh_t2t[(size_t)NT * DIM];
__device__ __half g_h16[(size_t)(NT + NC) * DIM];

#define CNT_T2C 0
#define CNT_C2T NC
#define CNT_C2C (NC + NT)
#define CNT_T2T (NC + NT + NC)
#define CNT_TOTAL (2 * NC + 2 * NT)
__device__ int g_cnt[CNT_TOTAL];
__device__ int g_off_t2c[NC + 1]; __device__ int g_pos_t2c[NC]; __device__ int g_e_t2c[E_T2C];
__device__ int g_off_c2t[NT + 1]; __device__ int g_pos_c2t[NT]; __device__ int g_e_c2t[E_C2T];
__device__ int g_off_c2c[NC + 1]; __device__ int g_pos_c2c[NC]; __device__ int g_e_c2c[E_C2C];
__device__ int g_off_t2t[NT + 1]; __device__ int g_pos_t2t[NT]; __device__ int g_e_t2t[E_T2T];

// scan partials: chunks per etype: NC->79, NT->20, NC->79, NT->20
#define NCH0 79
#define NCH1 20
#define NCH2 79
#define NCH3 20
#define NCH_TOTAL (NCH0 + NCH1 + NCH2 + NCH3)   // 198
__device__ int g_part[NCH_TOTAL];

// ---------------- helpers ----------------------------------------------------
__device__ __forceinline__ uint32_t smem_u32(const void* p) {
    uint32_t a;
    asm("{ .reg .u64 t; cvta.to.shared.u64 t, %1; cvt.u32.u64 %0, t; }" : "=r"(a) : "l"(p));
    return a;
}
#define CP_ASYNC16(dst, src) \
    asm volatile("cp.async.cg.shared.global [%0], [%1], 16;" :: "r"(dst), "l"(src))
#define CP_COMMIT() asm volatile("cp.async.commit_group;" ::: "memory")
#define CP_WAIT1() asm volatile("cp.async.wait_group 1;" ::: "memory")
#define CP_WAIT0() asm volatile("cp.async.wait_group 0;" ::: "memory")

__device__ __forceinline__ int warp_iscan(int v, int lane) {
    #pragma unroll
    for (int ofs = 1; ofs < 32; ofs <<= 1) {
        int t = __shfl_up_sync(0xffffffffu, v, ofs);
        if (lane >= ofs) v += t;
    }
    return v;
}

// map scan block id -> (cnt base, n, local chunk)
__device__ __forceinline__ void scan_map(int b, int& base, int& n, int& ch) {
    if (b < NCH0)                      { base = CNT_T2C; n = NC; ch = b; }
    else if (b < NCH0 + NCH1)          { base = CNT_C2T; n = NT; ch = b - NCH0; }
    else if (b < NCH0 + NCH1 + NCH2)   { base = CNT_C2C; n = NC; ch = b - NCH0 - NCH1; }
    else                               { base = CNT_T2T; n = NT; ch = b - NCH0 - NCH1 - NCH2; }
}

// ---------------- conversion kernels -----------------------------------------
__global__ void cvt_feat_kernel(const float* __restrict__ ft, const float* __restrict__ fc,
                                __half* __restrict__ dst) {
    int i = blockIdx.x * blockDim.x + threadIdx.x;
    const int n4T = NT * DIM / 4;
    const int n4 = (NT + NC) * DIM / 4;
    if (i >= n4) return;
    float4 v = (i < n4T) ? ((const float4*)ft)[i] : ((const float4*)fc)[i - n4T];
    half2* d2 = (half2*)dst;
    d2[2 * i]     = __floats2half2_rn(v.x, v.y);
    d2[2 * i + 1] = __floats2half2_rn(v.z, v.w);
}

__global__ void cvt_w_kernel(const float* __restrict__ w0, const float* __restrict__ w1,
                             const float* __restrict__ w2, const float* __restrict__ w3,
                             const float* __restrict__ w4, __half* __restrict__ dst) {
    int i = blockIdx.x * blockDim.x + threadIdx.x;
    if (i >= 5 * 16384) return;
    const float* srcs[5] = {w0, w1, w2, w3, w4};
    const float* s = srcs[i >> 14];
    int j = i & 16383;
    float4 v = ((const float4*)s)[j];
    half2* d2 = (half2*)dst;
    d2[2 * i]     = __floats2half2_rn(v.x, v.y);
    d2[2 * i + 1] = __floats2half2_rn(v.z, v.w);
}

// ---------------- graph preprocessing ----------------------------------------
__global__ void hist4_kernel(const int* __restrict__ d0, const int* __restrict__ d1,
                             const int* __restrict__ d2, const int* __restrict__ d3,
                             int* __restrict__ cnt,
                             int E0, int E1, int E2, int E3) {
    int i = blockIdx.x * blockDim.x + threadIdx.x;
    if (i < E0) { atomicAdd(&cnt[CNT_T2C + d0[i]], 1); return; }
    i -= E0;
    if (i < E1) { atomicAdd(&cnt[CNT_C2T + d1[i]], 1); return; }
    i -= E1;
    if (i < E2) { atomicAdd(&cnt[CNT_C2C + d2[i]], 1); return; }
    i -= E2;
    if (i < E3) { atomicAdd(&cnt[CNT_T2T + d3[i]], 1); }
}

// phase 1: per-chunk block-reduce sums (198 blocks, 1024 threads)
__global__ void scan_part_kernel(const int* __restrict__ cntbase, int* __restrict__ part) {
    int base, n, ch;
    scan_map(blockIdx.x, base, n, ch);
    const int tid = threadIdx.x, lane = tid & 31, warp = tid >> 5;
    int i = ch * 1024 + tid;
    int v = (i < n) ? cntbase[base + i] : 0;
    #pragma unroll
    for (int ofs = 16; ofs > 0; ofs >>= 1) v += __shfl_down_sync(0xffffffffu, v, ofs);
    __shared__ int ws[32];
    if (lane == 0) ws[warp] = v;
    __syncthreads();
    if (warp == 0) {
        int s = ws[lane];
        #pragma unroll
        for (int ofs = 16; ofs > 0; ofs >>= 1) s += __shfl_down_sync(0xffffffffu, s, ofs);
        if (lane == 0) part[blockIdx.x] = s;
    }
}

// phase 2: serial scan of 198 partials with per-etype resets (1 block)
__global__ void scan_mid_kernel(int* __restrict__ part,
                                int* o0, int* o1, int* o2, int* o3) {
    __shared__ int sh[NCH_TOTAL];
    const int tid = threadIdx.x;
    for (int i = tid; i < NCH_TOTAL; i += blockDim.x) sh[i] = part[i];
    __syncthreads();
    if (tid == 0) {
        const int bnd[5] = {0, NCH0, NCH0 + NCH1, NCH0 + NCH1 + NCH2, NCH_TOTAL};
        int* offs[4] = {o0, o1, o2, o3};
        const int nlist[4] = {NC, NT, NC, NT};
        for (int e = 0; e < 4; e++) {
            int run = 0;
            for (int b = bnd[e]; b < bnd[e + 1]; b++) { int v = sh[b]; sh[b] = run; run += v; }
            offs[e][nlist[e]] = run;
        }
    }
    __syncthreads();
    for (int i = tid; i < NCH_TOTAL; i += blockDim.x) part[i] = sh[i];
}

// phase 3: per-chunk scan + base, write off/pos (198 blocks)
__global__ void scan_out_kernel(const int* __restrict__ cntbase, const int* __restrict__ part,
                                int* o0, int* p0, int* o1, int* p1,
                                int* o2, int* p2, int* o3, int* p3) {
    int base, n, ch;
    scan_map(blockIdx.x, base, n, ch);
    int* off; int* pos;
    switch (base) {
        case CNT_T2C: off = o0; pos = p0; break;
        case CNT_C2T: off = o1; pos = p1; break;
        case CNT_C2C: off = o2; pos = p2; break;
        default:      off = o3; pos = p3; break;
    }
    const int tid = threadIdx.x, lane = tid & 31, warp = tid >> 5;
    int i = ch * 1024 + tid;
    int v = (i < n) ? cntbase[base + i] : 0;
    int incl = warp_iscan(v, lane);
    __shared__ int wpart[32];
    if (lane == 31) wpart[warp] = incl;
    __syncthreads();
    if (warp == 0) {
        int wv = wpart[lane];
        int ws = warp_iscan(wv, lane);
        wpart[lane] = ws - wv;
    }
    __syncthreads();
    int excl = part[blockIdx.x] + wpart[warp] + incl - v;
    if (i < n) { off[i] = excl; pos[i] = excl; }
}

__global__ void build4_kernel(const int* __restrict__ s0, const int* __restrict__ d0, int* p0, int* e0,
                              const int* __restrict__ s1, const int* __restrict__ d1, int* p1, int* e1,
                              const int* __restrict__ s2, const int* __restrict__ d2, int* p2, int* e2,
                              const int* __restrict__ s3, const int* __restrict__ d3, int* p3, int* e3,
                              int E0, int E1, int E2, int E3) {
    int i = blockIdx.x * blockDim.x + threadIdx.x;
    if (i < E0) { int sl = atomicAdd(&p0[d0[i]], 1); e0[sl] = s0[i]; return; }
    i -= E0;
    if (i < E1) { int sl = atomicAdd(&p1[d1[i]], 1); e1[sl] = s1[i]; return; }
    i -= E1;
    if (i < E2) { int sl = atomicAdd(&p2[d2[i]], 1); e2[sl] = s2[i]; return; }
    i -= E2;
    if (i < E3) { int sl = atomicAdd(&p3[d3[i]], 1); e3[sl] = s3[i]; }
}

// ---------------- fp16 GEMM core (KC=64, 2-stage cp.async) -------------------
#define AT_BYTES 18432
#define STG_BYTES 36864
#define GEMM_SMEM 73728

struct GemmCore {
    wmma::fragment<wmma::accumulator, 16, 16, 16, float> acc[2][4];
};

__device__ __forceinline__ void gemm_mainloop(
    const __half* __restrict__ A, const __half* __restrict__ W,
    char* smem, uint32_t sb, int bm, int M, int t, int wm, int wn,
    GemmCore& g) {
    #pragma unroll
    for (int i = 0; i < 2; i++)
        #pragma unroll
        for (int j = 0; j < 4; j++) wmma::fill_fragment(g.acc[i][j], 0.0f);

    auto prefetch = [&](int stage, int kb) {
        uint32_t baseA = sb + stage * STG_BYTES;
        uint32_t baseB = baseA + AT_BYTES;
        #pragma unroll
        for (int i = 0; i < 4; i++) {
            int idx = t + i * 256;
            int row = idx >> 3, seg = idx & 7;
            int grow = bm * 128 + row;
            if (grow > M - 1) grow = M - 1;
            CP_ASYNC16(baseA + (uint32_t)(row * 72 + seg * 8) * 2,
                       A + (size_t)grow * DIM + kb * 64 + seg * 8);
            CP_ASYNC16(baseB + (uint32_t)(row * 72 + seg * 8) * 2,
                       W + (size_t)row * DIM + kb * 64 + seg * 8);
        }
        CP_COMMIT();
    };

    prefetch(0, 0);

    for (int kb = 0; kb < 4; kb++) {
        const int s = kb & 1;
        if (kb < 3) { prefetch(s ^ 1, kb + 1); CP_WAIT1(); }
        else        { CP_WAIT0(); }
        __syncthreads();

        __half (*As)[72] = (__half(*)[72])(smem + s * STG_BYTES);
        __half (*Bs)[72] = (__half(*)[72])(smem + s * STG_BYTES + AT_BYTES);

        #pragma unroll
        for (int kk = 0; kk < 4; kk++) {
            wmma::fragment<wmma::matrix_a, 16, 16, 16, __half, wmma::row_major> a[2];
            wmma::fragment<wmma::matrix_b, 16, 16, 16, __half, wmma::col_major> b[4];
            #pragma unroll
            for (int i = 0; i < 2; i++)
                wmma::load_matrix_sync(a[i], &As[wm * 32 + i * 16][kk * 16], 72);
            #pragma unroll
            for (int j = 0; j < 4; j++)
                wmma::load_matrix_sync(b[j], &Bs[wn * 64 + j * 16][kk * 16], 72);
            #pragma unroll
            for (int i = 0; i < 2; i++)
                #pragma unroll
                for (int j = 0; j < 4; j++)
                    wmma::mma_sync(g.acc[i][j], a[i], b[j], g.acc[i][j]);
        }
        __syncthreads();
    }
}

// dual-weight Wh GEMM: grid (mtiles, 4); y>>1 selects weight/out, y&1 = col half
__global__ __launch_bounds__(256, 2)
void gemm_dual_kernel(const __half* __restrict__ A,
                      const __half* __restrict__ W0, const __half* __restrict__ W1,
                      const float* __restrict__ bias0, const float* __restrict__ bias1,
                      __half* __restrict__ out0, __half* __restrict__ out1, int M) {
    extern __shared__ __align__(16) char smem[];
    const int bm = blockIdx.x, by = blockIdx.y;
    const int which = by >> 1, bn = by & 1;
    const __half* W = which ? W1 : W0;
    const float* bias = which ? bias1 : bias0;
    __half* out = which ? out1 : out0;

    const int t = threadIdx.x;
    const int wid = t >> 5;
    const int wm = wid >> 1, wn = wid & 1;
    const uint32_t sb = smem_u32(smem);

    GemmCore g;
    gemm_mainloop(A, W + (size_t)bn * 128 * DIM, smem, sb, bm, M, t, wm, wn, g);

    float (*Cs)[32][68] = (float(*)[32][68])smem;
    #pragma unroll
    for (int w = 0; w < 2; w++) {
        if ((wid >> 2) == w) {
            int slot = wid & 3;
            #pragma unroll
            for (int i = 0; i < 2; i++)
                #pragma unroll
                for (int j = 0; j < 4; j++)
                    wmma::store_matrix_sync(&Cs[slot][i * 16][j * 16], g.acc[i][j], 68,
                                            wmma::mem_row_major);
        }
        __syncthreads();
        #pragma unroll
        for (int i = 0; i < 8; i++) {
            int idx = t + i * 256;
            int slot = idx >> 9;
            int within = idx & 511;
            int row = within >> 4, c4 = within & 15;
            int grow = bm * 128 + (w * 2 + (slot >> 1)) * 32 + row;
            if (grow >= M) continue;
            int col = bn * 128 + (slot & 1) * 64 + c4 * 4;
            float4 v = *(float4*)&Cs[slot][row][c4 * 4];
            float4 bb = *(const float4*)&bias[col];
            v.x += bb.x; v.y += bb.y; v.z += bb.z; v.w += bb.w;
            v.x = v.x >= 0.f ? v.x : 0.01f * v.x;
            v.y = v.y >= 0.f ? v.y : 0.01f * v.y;
            v.z = v.z >= 0.f ? v.z : 0.01f * v.z;
            v.w = v.w >= 0.f ? v.w : 0.01f * v.w;
            half2 h0 = __floats2half2_rn(v.x, v.y);
            half2 h1 = __floats2half2_rn(v.z, v.w);
            *(uint2*)&out[(size_t)grow * DIM + col] =
                make_uint2(*(uint32_t*)&h0, *(uint32_t*)&h1);
        }
        __syncthreads();
    }
}

// final GEMM: +residual, fp32 out. grid (mtiles, 2)
__global__ __launch_bounds__(256, 2)
void gemm_final_kernel(const __half* __restrict__ A, const __half* __restrict__ W,
                       const float* __restrict__ bias,
                       const float* __restrict__ resA, const float* __restrict__ resB,
                       int splitM, float* __restrict__ C, int M) {
    extern __shared__ __align__(16) char smem[];
    const int bm = blockIdx.x, bn = blockIdx.y;
    const int t = threadIdx.x;
    const int wid = t >> 5;
    const int wm = wid >> 1, wn = wid & 1;
    const uint32_t sb = smem_u32(smem);

    GemmCore g;
    gemm_mainloop(A, W + (size_t)bn * 128 * DIM, smem, sb, bm, M, t, wm, wn, g);

    float (*Cs)[32][68] = (float(*)[32][68])smem;
    #pragma unroll
    for (int w = 0; w < 2; w++) {
        if ((wid >> 2) == w) {
            int slot = wid & 3;
            #pragma unroll
            for (int i = 0; i < 2; i++)
                #pragma unroll
                for (int j = 0; j < 4; j++)
                    wmma::store_matrix_sync(&Cs[slot][i * 16][j * 16], g.acc[i][j], 68,
                                            wmma::mem_row_major);
        }
        __syncthreads();
        #pragma unroll
        for (int i = 0; i < 8; i++) {
            int idx = t + i * 256;
            int slot = idx >> 9;
            int within = idx & 511;
            int row = within >> 4, c4 = within & 15;
            int grow = bm * 128 + (w * 2 + (slot >> 1)) * 32 + row;
            if (grow >= M) continue;
            int col = bn * 128 + (slot & 1) * 64 + c4 * 4;
            float4 v = *(float4*)&Cs[slot][row][c4 * 4];
            float4 bb = *(const float4*)&bias[col];
            v.x += bb.x; v.y += bb.y; v.z += bb.z; v.w += bb.w;
            v.x = v.x >= 0.f ? v.x : 0.01f * v.x;
            v.y = v.y >= 0.f ? v.y : 0.01f * v.y;
            v.z = v.z >= 0.f ? v.z : 0.01f * v.z;
            v.w = v.w >= 0.f ? v.w : 0.01f * v.w;
            const float* rp = (grow < splitM)
                ? &resA[(size_t)grow * DIM + col]
                : &resB[(size_t)(grow - splitM) * DIM + col];
            float4 f = *(const float4*)rp;
            v.x += f.x; v.y += f.y; v.z += f.z; v.w += f.w;
            *(float4*)&C[(size_t)grow * DIM + col] = v;
        }
        __syncthreads();
    }
}

// ---------------- aggregation (fp16 in/out, fp32 accum, 4x MLP) --------------
__global__ void agg2_kernel(const __half* __restrict__ WhA, const int* __restrict__ offA,
                            const int* __restrict__ eA,
                            const __half* __restrict__ WhB, const int* __restrict__ offB,
                            const int* __restrict__ eB,
                            __half* __restrict__ h, int n) {
    int d = blockIdx.x * 8 + (threadIdx.x >> 5);
    int c = threadIdx.x & 31;
    if (d >= n) return;

    const uint4* A4 = (const uint4*)WhA;
    const uint4* B4 = (const uint4*)WhB;

    float acc[8];
    #pragma unroll
    for (int k = 0; k < 8; k++) acc[k] = 0.f;

    auto addv = [&](uint4 v) {
        half2* hv = (half2*)&v;
        #pragma unroll
        for (int k = 0; k < 4; k++) {
            float2 f = __half22float2(hv[k]);
            acc[2 * k] += f.x; acc[2 * k + 1] += f.y;
        }
    };

    auto run = [&](const uint4* T4, const int* e, int s0, int s1) {
        int j = s0;
        for (; j + 3 < s1; j += 4) {
            int i0 = __ldg(&e[j]),     i1 = __ldg(&e[j + 1]);
            int i2 = __ldg(&e[j + 2]), i3 = __ldg(&e[j + 3]);
            uint4 v0 = __ldg(&T4[(size_t)i0 * 32 + c]);
            uint4 v1 = __ldg(&T4[(size_t)i1 * 32 + c]);
            uint4 v2 = __ldg(&T4[(size_t)i2 * 32 + c]);
            uint4 v3 = __ldg(&T4[(size_t)i3 * 32 + c]);
            addv(v0); addv(v1); addv(v2); addv(v3);
        }
        for (; j < s1; j++) addv(__ldg(&T4[(size_t)__ldg(&e[j]) * 32 + c]));
    };

    int s0 = offA[d], s1 = offA[d + 1];
    run(A4, eA, s0, s1);
    float invA = 0.5f / (float)max(s1 - s0, 1);
    float r[8];
    #pragma unroll
    for (int k = 0; k < 8; k++) { r[k] = acc[k] * invA; acc[k] = 0.f; }

    s0 = offB[d]; s1 = offB[d + 1];
    run(B4, eB, s0, s1);
    float invB = 0.5f / (float)max(s1 - s0, 1);
    #pragma unroll
    for (int k = 0; k < 8; k++) r[k] += acc[k] * invB;

    uint4 o;
    half2 p0 = __floats2half2_rn(r[0], r[1]);
    half2 p1 = __floats2half2_rn(r[2], r[3]);
    half2 p2 = __floats2half2_rn(r[4], r[5]);
    half2 p3 = __floats2half2_rn(r[6], r[7]);
    o.x = *(uint32_t*)&p0; o.y = *(uint32_t*)&p1;
    o.z = *(uint32_t*)&p2; o.w = *(uint32_t*)&p3;
    ((uint4*)h)[(size_t)d * 32 + c] = o;
}

// ---------------- launch -----------------------------------------------------
extern "C" void kernel_launch(void* const* d_in, const int* in_sizes, int n_in,
                              void* d_out, int out_size) {
    const float* feat_table = (const float*)d_in[0];
    const float* feat_col   = (const float*)d_in[1];
    const float* W_t2c = (const float*)d_in[2];  const float* b_t2c = (const float*)d_in[3];
    const float* W_c2t = (const float*)d_in[4];  const float* b_c2t = (const float*)d_in[5];
    const float* W_c2c = (const float*)d_in[6];  const float* b_c2c = (const float*)d_in[7];
    const float* W_t2t = (const float*)d_in[8];  const float* b_t2t = (const float*)d_in[9];
    const float* W_h   = (const float*)d_in[10]; const float* b_h   = (const float*)d_in[11];
    const int* src_t2c = (const int*)d_in[12]; const int* dst_t2c = (const int*)d_in[13];
    const int* src_c2t = (const int*)d_in[14]; const int* dst_c2t = (const int*)d_in[15];
    const int* src_c2c = (const int*)d_in[16]; const int* dst_c2c = (const int*)d_in[17];
    const int* src_t2t = (const int*)d_in[18]; const int* dst_t2t = (const int*)d_in[19];
    float* out = (float*)d_out;

    __half *feat16, *W16, *Wh_t2c, *Wh_c2t, *Wh_c2c, *Wh_t2t, *h16;
    int *cnt, *part;
    int *off_t2c, *pos_t2c, *e_t2c;
    int *off_c2t, *pos_c2t, *e_c2t;
    int *off_c2c, *pos_c2c, *e_c2c;
    int *off_t2t, *pos_t2t, *e_t2t;
    cudaGetSymbolAddress((void**)&feat16, g_feat16);
    cudaGetSymbolAddress((void**)&W16, g_W16);
    cudaGetSymbolAddress((void**)&Wh_t2c, g_Wh_t2c);
    cudaGetSymbolAddress((void**)&Wh_c2t, g_Wh_c2t);
    cudaGetSymbolAddress((void**)&Wh_c2c, g_Wh_c2c);
    cudaGetSymbolAddress((void**)&Wh_t2t, g_Wh_t2t);
    cudaGetSymbolAddress((void**)&h16, g_h16);
    cudaGetSymbolAddress((void**)&cnt, g_cnt);
    cudaGetSymbolAddress((void**)&part, g_part);
    cudaGetSymbolAddress((void**)&off_t2c, g_off_t2c); cudaGetSymbolAddress((void**)&pos_t2c, g_pos_t2c);
    cudaGetSymbolAddress((void**)&e_t2c, g_e_t2c);
    cudaGetSymbolAddress((void**)&off_c2t, g_off_c2t); cudaGetSymbolAddress((void**)&pos_c2t, g_pos_c2t);
    cudaGetSymbolAddress((void**)&e_c2t, g_e_c2t);
    cudaGetSymbolAddress((void**)&off_c2c, g_off_c2c); cudaGetSymbolAddress((void**)&pos_c2c, g_pos_c2c);
    cudaGetSymbolAddress((void**)&e_c2c, g_e_c2c);
    cudaGetSymbolAddress((void**)&off_t2t, g_off_t2t); cudaGetSymbolAddress((void**)&pos_t2t, g_pos_t2t);
    cudaGetSymbolAddress((void**)&e_t2t, g_e_t2t);

    cudaFuncSetAttribute(gemm_dual_kernel,  cudaFuncAttributeMaxDynamicSharedMemorySize, GEMM_SMEM);
    cudaFuncSetAttribute(gemm_final_kernel, cudaFuncAttributeMaxDynamicSharedMemorySize, GEMM_SMEM);

    const int Et2c = in_sizes[12], Ec2t = in_sizes[14], Ec2c = in_sizes[16], Et2t = in_sizes[18];
    const int Eall = Et2c + Ec2t + Ec2c + Et2t;

    cvt_feat_kernel<<<((NT + NC) * DIM / 4 + 255) / 256, 256>>>(feat_table, feat_col, feat16);
    cvt_w_kernel<<<(5 * 16384 + 255) / 256, 256>>>(W_t2c, W_c2t, W_c2c, W_t2t, W_h, W16);

    cudaMemsetAsync(cnt, 0, CNT_TOTAL * sizeof(int), 0);
    hist4_kernel<<<(Eall + 255) / 256, 256>>>(dst_t2c, dst_c2t, dst_c2c, dst_t2t,
                                              cnt, Et2c, Ec2t, Ec2c, Et2t);

    scan_part_kernel<<<NCH_TOTAL, 1024>>>(cnt, part);
    scan_mid_kernel<<<1, 256>>>(part, off_t2c, off_c2t, off_c2c, off_t2t);
    scan_out_kernel<<<NCH_TOTAL, 1024>>>(cnt, part,
                                         off_t2c, pos_t2c, off_c2t, pos_c2t,
                                         off_c2c, pos_c2c, off_t2t, pos_t2t);

    build4_kernel<<<(Eall + 255) / 256, 256>>>(
        src_t2c, dst_t2c, pos_t2c, e_t2c,
        src_c2t, dst_c2t, pos_c2t, e_c2t,
        src_c2c, dst_c2c, pos_c2c, e_c2c,
        src_t2t, dst_t2t, pos_t2t, e_t2t,
        Et2c, Ec2t, Ec2c, Et2t);

    const __half* featT16 = feat16;
    const __half* featC16 = feat16 + (size_t)NT * DIM;
    const int gT = (NT + 127) / 128, gC = (NC + 127) / 128, gAll = (NT + NC + 127) / 128;

    gemm_dual_kernel<<<dim3(gT, 4), 256, GEMM_SMEM>>>(
        featT16, W16 + 0 * DIM * DIM, W16 + 3 * DIM * DIM, b_t2c, b_t2t,
        Wh_t2c, Wh_t2t, NT);
    gemm_dual_kernel<<<dim3(gC, 4), 256, GEMM_SMEM>>>(
        featC16, W16 + 1 * DIM * DIM, W16 + 2 * DIM * DIM, b_c2t, b_c2c,
        Wh_c2t, Wh_c2c, NC);

    agg2_kernel<<<(NT + 7) / 8, 256>>>(Wh_c2t, off_c2t, e_c2t, Wh_t2t, off_t2t, e_t2t, h16, NT);
    agg2_kernel<<<(NC + 7) / 8, 256>>>(Wh_t2c, off_t2c, e_t2c, Wh_c2c, off_c2c, e_c2c,
                                       h16 + (size_t)NT * DIM, NC);

    gemm_final_kernel<<<dim3(gAll, 2), 256, GEMM_SMEM>>>(
        h16, W16 + 4 * DIM * DIM, b_h, feat_table, feat_col, NT, out, NT + NC);
}